// round 2
// baseline (speedup 1.0000x reference)
#include <cuda_runtime.h>
#include <cstdint>

// Problem constants
#define BATCH 8
#define SEQ   4096
#define EMB   512
#define NHEAD 8
#define HDIM  64
#define BS_ROWS (BATCH*SEQ)          // 32768
#define NCHUNK 8                     // S-chunks for kv partial accumulation

// Scratch (device globals: allocation-free contract)
__device__ float g_q [BS_ROWS * EMB];
__device__ float g_k [BS_ROWS * EMB];
__device__ float g_v [BS_ROWS * EMB];
__device__ float g_o [BS_ROWS * EMB];
__device__ float g_kvp[NCHUNK * 64 * HDIM * HDIM];  // [chunk][bh][d][m]
__device__ float g_ksp[NCHUNK * 64 * HDIM];         // [chunk][bh][d]

// ---------------------------------------------------------------------------
// SGEMM: C[M,N] = A[M,K] @ B[K,N] + bias[N], optional elu(x)+1 epilogue.
// 128x128 block tile, BK=16, 8x8 per thread, 256 threads.
// ---------------------------------------------------------------------------
__global__ __launch_bounds__(256, 2)
void sgemm_bias_act(const float* __restrict__ A, const float* __restrict__ B,
                    const float* __restrict__ bias, float* __restrict__ C,
                    int M, int N, int K, int act)
{
    const int BM = 128, BN = 128, BK = 16, TM = 8, TN = 8;
    __shared__ float As[BK][BM];
    __shared__ float Bs[BK][BN];

    const int tid  = threadIdx.x;
    const int brow = blockIdx.y;
    const int bcol = blockIdx.x;

    const float* Ab = A + (size_t)brow * BM * K;
    const float* Bb = B + (size_t)bcol * BN;

    float acc[TM][TN];
#pragma unroll
    for (int i = 0; i < TM; i++)
#pragma unroll
        for (int j = 0; j < TN; j++) acc[i][j] = 0.f;

    const int tr  = tid / 16;          // 0..15 (M micro-tile)
    const int tc  = tid % 16;          // 0..15 (N micro-tile)
    const int arow = tid >> 2;         // A load: 64 rows/pass, 2 passes
    const int ac4  = (tid & 3) * 4;
    const int brw  = tid >> 5;         // B load: 8 rows/pass, 2 passes
    const int bc4  = (tid & 31) * 4;

    for (int kt = 0; kt < K; kt += BK) {
#pragma unroll
        for (int i = 0; i < 2; i++) {
            int r = arow + i * 64;
            float4 a = *reinterpret_cast<const float4*>(&Ab[(size_t)r * K + kt + ac4]);
            As[ac4 + 0][r] = a.x;
            As[ac4 + 1][r] = a.y;
            As[ac4 + 2][r] = a.z;
            As[ac4 + 3][r] = a.w;
        }
#pragma unroll
        for (int i = 0; i < 2; i++) {
            int r = brw + i * 8;
            float4 bv = *reinterpret_cast<const float4*>(&Bb[(size_t)(kt + r) * N + bc4]);
            *reinterpret_cast<float4*>(&Bs[r][bc4]) = bv;
        }
        __syncthreads();

#pragma unroll
        for (int k = 0; k < BK; k++) {
            float rm[TM], rn[TN];
#pragma unroll
            for (int i = 0; i < TM; i += 4) {
                float4 t = *reinterpret_cast<const float4*>(&As[k][tr * TM + i]);
                rm[i] = t.x; rm[i+1] = t.y; rm[i+2] = t.z; rm[i+3] = t.w;
            }
#pragma unroll
            for (int j = 0; j < TN; j += 4) {
                float4 t = *reinterpret_cast<const float4*>(&Bs[k][tc * TN + j]);
                rn[j] = t.x; rn[j+1] = t.y; rn[j+2] = t.z; rn[j+3] = t.w;
            }
#pragma unroll
            for (int i = 0; i < TM; i++)
#pragma unroll
                for (int j = 0; j < TN; j++)
                    acc[i][j] += rm[i] * rn[j];
        }
        __syncthreads();
    }

    // Epilogue: bias + optional feature map (elu(x)+1)
    const int colbase = bcol * BN + tc * TN;
#pragma unroll
    for (int i = 0; i < TM; i++) {
        size_t row = (size_t)brow * BM + tr * TM + i;
#pragma unroll
        for (int j = 0; j < TN; j += 4) {
            float4 o;
            float v0 = acc[i][j+0] + bias[colbase + j + 0];
            float v1 = acc[i][j+1] + bias[colbase + j + 1];
            float v2 = acc[i][j+2] + bias[colbase + j + 2];
            float v3 = acc[i][j+3] + bias[colbase + j + 3];
            if (act) {
                v0 = (v0 > 0.f) ? v0 + 1.f : __expf(v0);
                v1 = (v1 > 0.f) ? v1 + 1.f : __expf(v1);
                v2 = (v2 > 0.f) ? v2 + 1.f : __expf(v2);
                v3 = (v3 > 0.f) ? v3 + 1.f : __expf(v3);
            }
            o.x = v0; o.y = v1; o.z = v2; o.w = v3;
            *reinterpret_cast<float4*>(&C[row * N + colbase + j]) = o;
        }
    }
}

// ---------------------------------------------------------------------------
// kv partial kernel: per (b,h) and per S-chunk of 512, accumulate
//   kvp[d][m] = sum_s k[s][d] * v[s][m]   and   ksp[d] = sum_s k[s][d]
// grid (64, NCHUNK), 256 threads. No atomics: partials reduced by consumer.
// ---------------------------------------------------------------------------
__global__ __launch_bounds__(256)
void kv_kernel(const float* __restrict__ K, const float* __restrict__ V,
               float* __restrict__ KVP, float* __restrict__ KSP)
{
    __shared__ float ks_s[8][64];
    __shared__ float vs_s[8][64];

    const int tid = threadIdx.x;
    const int bh = blockIdx.x;
    const int b = bh >> 3, h = bh & 7;
    const int chunk = blockIdx.y;
    const int s0 = chunk * 512;

    const int m  = tid & 63;
    const int dg = tid >> 6;
    const int d0 = dg * 16;

    float acc[16];
#pragma unroll
    for (int j = 0; j < 16; j++) acc[j] = 0.f;
    float ksacc = 0.f;

    for (int sb = 0; sb < 512; sb += 8) {
#pragma unroll
        for (int i = 0; i < 2; i++) {
            int lin = i * 256 + tid;
            int sr = lin >> 6, dd = lin & 63;
            size_t off = ((size_t)(b * SEQ + s0 + sb + sr)) * EMB + h * HDIM + dd;
            ks_s[sr][dd] = K[off];
            vs_s[sr][dd] = V[off];
        }
        __syncthreads();
#pragma unroll
        for (int ss = 0; ss < 8; ss++) {
            float vm = vs_s[ss][m];
#pragma unroll
            for (int j = 0; j < 16; j++)
                acc[j] += ks_s[ss][d0 + j] * vm;
        }
        if (tid < 64) {
#pragma unroll
            for (int ss = 0; ss < 8; ss++) ksacc += ks_s[ss][tid];
        }
        __syncthreads();
    }

    float* kvp = KVP + ((size_t)chunk * 64 + bh) * (HDIM * HDIM);
#pragma unroll
    for (int j = 0; j < 16; j++)
        kvp[(d0 + j) * HDIM + m] = acc[j];
    if (tid < 64)
        KSP[((size_t)chunk * 64 + bh) * HDIM + tid] = ksacc;
}

// ---------------------------------------------------------------------------
// Attention output kernel: per (b,h) load kv (reduced over chunks) to smem,
// then per token: z = 1/(q.ksum+eps), o[m] = z * sum_d q[d]*kv[d][m].
// grid (64, 16), 256 threads; 16 tokens in flight, 4 m-values per thread.
// ---------------------------------------------------------------------------
__global__ __launch_bounds__(256)
void attn_kernel(const float* __restrict__ Q, const float* __restrict__ KVP,
                 const float* __restrict__ KSP, float* __restrict__ O)
{
    __shared__ float kv_s[64 * 64];   // [d][m]
    __shared__ float ks_s[64];
    __shared__ float q_s[16][64];

    const int tid = threadIdx.x;
    const int bh = blockIdx.x;
    const int b = bh >> 3, h = bh & 7;
    const int s0 = blockIdx.y * 256;

    // reduce kv partials over NCHUNK chunks (hits L2: buffer is 8 MB, 16x reuse)
    for (int i = tid; i < 64 * 64; i += 256) {
        float sum = 0.f;
#pragma unroll
        for (int c = 0; c < NCHUNK; c++)
            sum += KVP[((size_t)c * 64 + bh) * (HDIM * HDIM) + i];
        kv_s[i] = sum;
    }
    if (tid < 64) {
        float sum = 0.f;
#pragma unroll
        for (int c = 0; c < NCHUNK; c++)
            sum += KSP[((size_t)c * 64 + bh) * HDIM + tid];
        ks_s[tid] = sum;
    }
    __syncthreads();

    const int mg = tid & 15;           // m-group: 4 consecutive m
    const int ts = tid >> 4;           // token slot 0..15
    const int m0 = mg * 4;

    for (int it = 0; it < 16; it++) {
        // stage q for 16 tokens
#pragma unroll
        for (int i = 0; i < 4; i++) {
            int lin = i * 256 + tid;
            int trw = lin >> 6, d = lin & 63;
            int s = s0 + it * 16 + trw;
            q_s[trw][d] = Q[((size_t)(b * SEQ + s)) * EMB + h * HDIM + d];
        }
        __syncthreads();

        float n0 = 0.f, n1 = 0.f, n2 = 0.f, n3 = 0.f, zd = 0.f;
#pragma unroll 16
        for (int d = 0; d < 64; d++) {
            float qd = q_s[ts][d];
            float4 kvv = *reinterpret_cast<const float4*>(&kv_s[d * 64 + m0]);
            n0 += qd * kvv.x;
            n1 += qd * kvv.y;
            n2 += qd * kvv.z;
            n3 += qd * kvv.w;
            zd += qd * ks_s[d];
        }
        float z = 1.f / (zd + 1e-6f);
        int s = s0 + it * 16 + ts;
        float4 o4 = make_float4(n0 * z, n1 * z, n2 * z, n3 * z);
        *reinterpret_cast<float4*>(&O[((size_t)(b * SEQ + s)) * EMB + h * HDIM + m0]) = o4;
        __syncthreads();
    }
}

// ---------------------------------------------------------------------------
extern "C" void kernel_launch(void* const* d_in, const int* in_sizes, int n_in,
                              void* d_out, int out_size)
{
    const float* x  = (const float*)d_in[0];
    const float* Wq = (const float*)d_in[1];
    const float* bq = (const float*)d_in[2];
    const float* Wk = (const float*)d_in[3];
    const float* bk = (const float*)d_in[4];
    const float* Wv = (const float*)d_in[5];
    const float* bv = (const float*)d_in[6];
    const float* Wo = (const float*)d_in[7];
    const float* bo = (const float*)d_in[8];
    float* out = (float*)d_out;

    float *qp, *kp, *vp, *op, *kvp, *ksp;
    cudaGetSymbolAddress((void**)&qp,  g_q);
    cudaGetSymbolAddress((void**)&kp,  g_k);
    cudaGetSymbolAddress((void**)&vp,  g_v);
    cudaGetSymbolAddress((void**)&op,  g_o);
    cudaGetSymbolAddress((void**)&kvp, g_kvp);
    cudaGetSymbolAddress((void**)&ksp, g_ksp);

    dim3 gemm_grid(EMB / 128, BS_ROWS / 128);   // (4, 256)

    sgemm_bias_act<<<gemm_grid, 256>>>(x, Wq, bq, qp, BS_ROWS, EMB, EMB, 1);
    sgemm_bias_act<<<gemm_grid, 256>>>(x, Wk, bk, kp, BS_ROWS, EMB, EMB, 1);
    sgemm_bias_act<<<gemm_grid, 256>>>(x, Wv, bv, vp, BS_ROWS, EMB, EMB, 0);

    kv_kernel<<<dim3(64, NCHUNK), 256>>>(kp, vp, kvp, ksp);
    attn_kernel<<<dim3(64, 16), 256>>>(qp, kvp, ksp, op);

    sgemm_bias_act<<<gemm_grid, 256>>>(op, Wo, bo, out, BS_ROWS, EMB, EMB, 0);
}

// round 4
// speedup vs baseline: 2.3015x; 2.3015x over previous
#include <cuda_runtime.h>
#include <cstdint>

// Problem constants
#define BATCH 8
#define SEQ   4096
#define EMB   512
#define NHEAD 8
#define HDIM  64
#define BS_ROWS (BATCH*SEQ)          // 32768
#define NCHUNK 8

// Scratch (device globals: allocation-free contract)
__device__ float g_q [BS_ROWS * EMB];
__device__ float g_k [BS_ROWS * EMB];
__device__ float g_v [BS_ROWS * EMB];
__device__ float g_o [BS_ROWS * EMB];
__device__ float g_kvp[NCHUNK * 64 * HDIM * HDIM];
__device__ float g_ksp[NCHUNK * 64 * HDIM];
__device__ float g_wt [4 * EMB * EMB];              // transposed weights [N,K]

// ---------------------------------------------------------------------------
// tf32 helpers (baseline PTX, no arch-specific features)
// ---------------------------------------------------------------------------
__device__ __forceinline__ uint32_t f2tf(float f) {
    uint32_t u;
    asm("cvt.rna.tf32.f32 %0, %1;" : "=r"(u) : "f"(f));
    return u;
}

__device__ __forceinline__ void mma_tf32(float* d, const uint32_t* a, const uint32_t* b) {
    asm volatile(
        "mma.sync.aligned.m16n8k8.row.col.f32.tf32.tf32.f32 "
        "{%0,%1,%2,%3}, {%4,%5,%6,%7}, {%8,%9}, {%0,%1,%2,%3};"
        : "+f"(d[0]), "+f"(d[1]), "+f"(d[2]), "+f"(d[3])
        : "r"(a[0]), "r"(a[1]), "r"(a[2]), "r"(a[3]), "r"(b[0]), "r"(b[1]));
}

// ---------------------------------------------------------------------------
// Weight transpose: Wt[n][k] = W[k][n], 512x512
// ---------------------------------------------------------------------------
__global__ __launch_bounds__(256)
void transpose512(const float* __restrict__ W, float* __restrict__ Wt) {
    __shared__ float t[32][33];
    int bx = blockIdx.x * 32, by = blockIdx.y * 32;
    int x = threadIdx.x & 31, y = threadIdx.x >> 5;   // 32x8
#pragma unroll
    for (int i = 0; i < 32; i += 8) t[y + i][x] = W[(size_t)(by + y + i) * 512 + bx + x];
    __syncthreads();
#pragma unroll
    for (int i = 0; i < 32; i += 8) Wt[(size_t)(bx + y + i) * 512 + by + x] = t[x][y + i];
}

// ---------------------------------------------------------------------------
// tf32 mma.sync GEMM: C[M,512] = A[M,512] @ Bt[512,512]^T + bias (opt elu+1)
// A row-major [M,K], Bt row-major [N,K]. Tile 128x128, BK=32.
// 128 threads = 4 warps, warp tile 64x64 (mt=4 x nt=8 of m16n8k8).
// ---------------------------------------------------------------------------
template <int ACT>
__global__ __launch_bounds__(128, 2)
void gemm_mma(const float* __restrict__ A, const float* __restrict__ Bt,
              const float* __restrict__ bias, float* __restrict__ C)
{
    __shared__ float As[128][36];
    __shared__ float Bs[128][36];

    const int tid = threadIdx.x;
    const int wid = tid >> 5;
    const int lid = tid & 31;
    const int gid = lid >> 2;          // 0..7
    const int tig = lid & 3;           // 0..3
    const int wm  = wid & 1;           // warp m position (0..1)
    const int wn  = wid >> 1;          // warp n position (0..1)

    const float* Ab = A  + (size_t)blockIdx.y * 128 * 512;
    const float* Bb = Bt + (size_t)blockIdx.x * 128 * 512;

    float acc[4][8][4];
#pragma unroll
    for (int mt = 0; mt < 4; mt++)
#pragma unroll
        for (int nt = 0; nt < 8; nt++)
#pragma unroll
            for (int f = 0; f < 4; f++) acc[mt][nt][f] = 0.f;

    for (int s = 0; s < 16; s++) {
        // --- global loads for this stage (two batches of 4 float4 each) ---
        float4 a4[4], b4[4], a4b[4], b4b[4];
#pragma unroll
        for (int i = 0; i < 4; i++) {
            int idx = i * 128 + tid;
            int row = idx >> 3, c4 = idx & 7;
            a4[i] = *reinterpret_cast<const float4*>(&Ab[(size_t)row * 512 + s * 32 + c4 * 4]);
            b4[i] = *reinterpret_cast<const float4*>(&Bb[(size_t)row * 512 + s * 32 + c4 * 4]);
        }
#pragma unroll
        for (int i = 0; i < 4; i++) {
            int idx = (i + 4) * 128 + tid;
            int row = idx >> 3, c4 = idx & 7;
            a4b[i] = *reinterpret_cast<const float4*>(&Ab[(size_t)row * 512 + s * 32 + c4 * 4]);
            b4b[i] = *reinterpret_cast<const float4*>(&Bb[(size_t)row * 512 + s * 32 + c4 * 4]);
        }

        __syncthreads();   // all warps done reading smem from previous stage

#pragma unroll
        for (int i = 0; i < 4; i++) {
            int idx = i * 128 + tid;
            int row = idx >> 3, c4 = idx & 7;
            uint4 ta = make_uint4(f2tf(a4[i].x), f2tf(a4[i].y), f2tf(a4[i].z), f2tf(a4[i].w));
            uint4 tb = make_uint4(f2tf(b4[i].x), f2tf(b4[i].y), f2tf(b4[i].z), f2tf(b4[i].w));
            *reinterpret_cast<uint4*>(&As[row][c4 * 4]) = ta;
            *reinterpret_cast<uint4*>(&Bs[row][c4 * 4]) = tb;
        }
#pragma unroll
        for (int i = 0; i < 4; i++) {
            int idx = (i + 4) * 128 + tid;
            int row = idx >> 3, c4 = idx & 7;
            uint4 ta = make_uint4(f2tf(a4b[i].x), f2tf(a4b[i].y), f2tf(a4b[i].z), f2tf(a4b[i].w));
            uint4 tb = make_uint4(f2tf(b4b[i].x), f2tf(b4b[i].y), f2tf(b4b[i].z), f2tf(b4b[i].w));
            *reinterpret_cast<uint4*>(&As[row][c4 * 4]) = ta;
            *reinterpret_cast<uint4*>(&Bs[row][c4 * 4]) = tb;
        }

        __syncthreads();   // smem tiles visible

        // --- 4 k8-steps of MMA ---
#pragma unroll
        for (int k8 = 0; k8 < 4; k8++) {
            const int k0 = k8 * 8;
            uint32_t af[4][4];
#pragma unroll
            for (int mt = 0; mt < 4; mt++) {
                int m0 = wm * 64 + mt * 16 + gid;
                af[mt][0] = __float_as_uint(As[m0    ][k0 + tig    ]);
                af[mt][1] = __float_as_uint(As[m0 + 8][k0 + tig    ]);
                af[mt][2] = __float_as_uint(As[m0    ][k0 + tig + 4]);
                af[mt][3] = __float_as_uint(As[m0 + 8][k0 + tig + 4]);
            }
            uint32_t bf[8][2];
#pragma unroll
            for (int nt = 0; nt < 8; nt++) {
                int n0 = wn * 64 + nt * 8 + gid;
                bf[nt][0] = __float_as_uint(Bs[n0][k0 + tig    ]);
                bf[nt][1] = __float_as_uint(Bs[n0][k0 + tig + 4]);
            }
#pragma unroll
            for (int mt = 0; mt < 4; mt++)
#pragma unroll
                for (int nt = 0; nt < 8; nt++)
                    mma_tf32(acc[mt][nt], af[mt], bf[nt]);
        }
    }

    // --- epilogue: bias + optional elu(x)+1, direct float2 stores ---
#pragma unroll
    for (int mt = 0; mt < 4; mt++) {
        size_t r0 = (size_t)blockIdx.y * 128 + wm * 64 + mt * 16 + gid;
#pragma unroll
        for (int nt = 0; nt < 8; nt++) {
            int col = blockIdx.x * 128 + wn * 64 + nt * 8 + tig * 2;
            float bb0 = bias[col], bb1 = bias[col + 1];
            float v0 = acc[mt][nt][0] + bb0;
            float v1 = acc[mt][nt][1] + bb1;
            float v2 = acc[mt][nt][2] + bb0;
            float v3 = acc[mt][nt][3] + bb1;
            if (ACT) {
                v0 = (v0 > 0.f) ? v0 + 1.f : __expf(v0);
                v1 = (v1 > 0.f) ? v1 + 1.f : __expf(v1);
                v2 = (v2 > 0.f) ? v2 + 1.f : __expf(v2);
                v3 = (v3 > 0.f) ? v3 + 1.f : __expf(v3);
            }
            *reinterpret_cast<float2*>(&C[r0 * 512 + col])       = make_float2(v0, v1);
            *reinterpret_cast<float2*>(&C[(r0 + 8) * 512 + col]) = make_float2(v2, v3);
        }
    }
}

// ---------------------------------------------------------------------------
// kv partial kernel (unchanged, known-good from R2)
// ---------------------------------------------------------------------------
__global__ __launch_bounds__(256)
void kv_kernel(const float* __restrict__ K, const float* __restrict__ V,
               float* __restrict__ KVP, float* __restrict__ KSP)
{
    __shared__ float ks_s[8][64];
    __shared__ float vs_s[8][64];

    const int tid = threadIdx.x;
    const int bh = blockIdx.x;
    const int b = bh >> 3, h = bh & 7;
    const int chunk = blockIdx.y;
    const int s0 = chunk * 512;

    const int m  = tid & 63;
    const int dg = tid >> 6;
    const int d0 = dg * 16;

    float acc[16];
#pragma unroll
    for (int j = 0; j < 16; j++) acc[j] = 0.f;
    float ksacc = 0.f;

    for (int sbk = 0; sbk < 512; sbk += 8) {
#pragma unroll
        for (int i = 0; i < 2; i++) {
            int lin = i * 256 + tid;
            int sr = lin >> 6, dd = lin & 63;
            size_t off = ((size_t)(b * SEQ + s0 + sbk + sr)) * EMB + h * HDIM + dd;
            ks_s[sr][dd] = K[off];
            vs_s[sr][dd] = V[off];
        }
        __syncthreads();
#pragma unroll
        for (int ss = 0; ss < 8; ss++) {
            float vm = vs_s[ss][m];
#pragma unroll
            for (int j = 0; j < 16; j++)
                acc[j] += ks_s[ss][d0 + j] * vm;
        }
        if (tid < 64) {
#pragma unroll
            for (int ss = 0; ss < 8; ss++) ksacc += ks_s[ss][tid];
        }
        __syncthreads();
    }

    float* kvp = KVP + ((size_t)chunk * 64 + bh) * (HDIM * HDIM);
#pragma unroll
    for (int j = 0; j < 16; j++)
        kvp[(d0 + j) * HDIM + m] = acc[j];
    if (tid < 64)
        KSP[((size_t)chunk * 64 + bh) * HDIM + tid] = ksacc;
}

// ---------------------------------------------------------------------------
// Attention output kernel (unchanged, known-good from R2)
// ---------------------------------------------------------------------------
__global__ __launch_bounds__(256)
void attn_kernel(const float* __restrict__ Q, const float* __restrict__ KVP,
                 const float* __restrict__ KSP, float* __restrict__ O)
{
    __shared__ float kv_s[64 * 64];
    __shared__ float ks_s[64];
    __shared__ float q_s[16][64];

    const int tid = threadIdx.x;
    const int bh = blockIdx.x;
    const int b = bh >> 3, h = bh & 7;
    const int s0 = blockIdx.y * 256;

    for (int i = tid; i < 64 * 64; i += 256) {
        float sum = 0.f;
#pragma unroll
        for (int c = 0; c < NCHUNK; c++)
            sum += KVP[((size_t)c * 64 + bh) * (HDIM * HDIM) + i];
        kv_s[i] = sum;
    }
    if (tid < 64) {
        float sum = 0.f;
#pragma unroll
        for (int c = 0; c < NCHUNK; c++)
            sum += KSP[((size_t)c * 64 + bh) * HDIM + tid];
        ks_s[tid] = sum;
    }
    __syncthreads();

    const int mg = tid & 15;
    const int ts = tid >> 4;
    const int m0 = mg * 4;

    for (int it = 0; it < 16; it++) {
#pragma unroll
        for (int i = 0; i < 4; i++) {
            int lin = i * 256 + tid;
            int trw = lin >> 6, d = lin & 63;
            int s = s0 + it * 16 + trw;
            q_s[trw][d] = Q[((size_t)(b * SEQ + s)) * EMB + h * HDIM + d];
        }
        __syncthreads();

        float n0 = 0.f, n1 = 0.f, n2 = 0.f, n3 = 0.f, zd = 0.f;
#pragma unroll 16
        for (int d = 0; d < 64; d++) {
            float qd = q_s[ts][d];
            float4 kvv = *reinterpret_cast<const float4*>(&kv_s[d * 64 + m0]);
            n0 += qd * kvv.x;
            n1 += qd * kvv.y;
            n2 += qd * kvv.z;
            n3 += qd * kvv.w;
            zd += qd * ks_s[d];
        }
        float z = 1.f / (zd + 1e-6f);
        int s = s0 + it * 16 + ts;
        float4 o4 = make_float4(n0 * z, n1 * z, n2 * z, n3 * z);
        *reinterpret_cast<float4*>(&O[((size_t)(b * SEQ + s)) * EMB + h * HDIM + m0]) = o4;
        __syncthreads();
    }
}

// ---------------------------------------------------------------------------
extern "C" void kernel_launch(void* const* d_in, const int* in_sizes, int n_in,
                              void* d_out, int out_size)
{
    const float* x  = (const float*)d_in[0];
    const float* Wq = (const float*)d_in[1];
    const float* bq = (const float*)d_in[2];
    const float* Wk = (const float*)d_in[3];
    const float* bk = (const float*)d_in[4];
    const float* Wv = (const float*)d_in[5];
    const float* bv = (const float*)d_in[6];
    const float* Wo = (const float*)d_in[7];
    const float* bo = (const float*)d_in[8];
    float* out = (float*)d_out;

    float *qp, *kp, *vp, *op, *kvp, *ksp, *wt;
    cudaGetSymbolAddress((void**)&qp,  g_q);
    cudaGetSymbolAddress((void**)&kp,  g_k);
    cudaGetSymbolAddress((void**)&vp,  g_v);
    cudaGetSymbolAddress((void**)&op,  g_o);
    cudaGetSymbolAddress((void**)&kvp, g_kvp);
    cudaGetSymbolAddress((void**)&ksp, g_ksp);
    cudaGetSymbolAddress((void**)&wt,  g_wt);

    float* wtq = wt;
    float* wtk = wt + EMB * EMB;
    float* wtv = wt + 2 * EMB * EMB;
    float* wto = wt + 3 * EMB * EMB;

    dim3 tgrid(16, 16);
    transpose512<<<tgrid, 256>>>(Wq, wtq);
    transpose512<<<tgrid, 256>>>(Wk, wtk);
    transpose512<<<tgrid, 256>>>(Wv, wtv);
    transpose512<<<tgrid, 256>>>(Wo, wto);

    dim3 ggrid(4, 256);
    gemm_mma<1><<<ggrid, 128>>>(x, wtq, bq, qp);
    gemm_mma<1><<<ggrid, 128>>>(x, wtk, bk, kp);
    gemm_mma<0><<<ggrid, 128>>>(x, wtv, bv, vp);

    kv_kernel<<<dim3(64, NCHUNK), 256>>>(kp, vp, kvp, ksp);
    attn_kernel<<<dim3(64, 16), 256>>>(qp, kvp, ksp, op);

    gemm_mma<0><<<ggrid, 128>>>(op, wto, bo, out);
}

// round 5
// speedup vs baseline: 3.7454x; 1.6274x over previous
#include <cuda_runtime.h>
#include <cuda_fp16.h>
#include <cstdint>

// Problem constants
#define BATCH 8
#define SEQ   4096
#define EMB   512
#define NHEAD 8
#define HDIM  64
#define BS_ROWS (BATCH*SEQ)          // 32768
#define NCHUNK 8

// Scratch (device globals: allocation-free contract)
__device__ __half g_xh [BS_ROWS * EMB];
__device__ __half g_qh [BS_ROWS * EMB];
__device__ __half g_kh [BS_ROWS * EMB];
__device__ __half g_vh [BS_ROWS * EMB];
__device__ __half g_oh [BS_ROWS * EMB];
__device__ __half g_wth[4 * EMB * EMB];            // transposed half weights [N][K]
__device__ float  g_kvp[NCHUNK * 64 * HDIM * HDIM];
__device__ float  g_ksp[NCHUNK * 64 * HDIM];

// ---------------------------------------------------------------------------
// fp16 mma helper (m16n8k16, f32 accumulate) — baseline PTX, sm_80+
// ---------------------------------------------------------------------------
__device__ __forceinline__ void mma_h(float* d, const uint32_t* a, uint32_t b0, uint32_t b1) {
    asm volatile(
        "mma.sync.aligned.m16n8k16.row.col.f32.f16.f16.f32 "
        "{%0,%1,%2,%3}, {%4,%5,%6,%7}, {%8,%9}, {%0,%1,%2,%3};"
        : "+f"(d[0]), "+f"(d[1]), "+f"(d[2]), "+f"(d[3])
        : "r"(a[0]), "r"(a[1]), "r"(a[2]), "r"(a[3]), "r"(b0), "r"(b1));
}

__device__ __forceinline__ void cp_async16(uint32_t smem_addr, const void* gptr) {
    asm volatile("cp.async.cg.shared.global [%0], [%1], 16;" :: "r"(smem_addr), "l"(gptr));
}
__device__ __forceinline__ void cp_commit() { asm volatile("cp.async.commit_group;"); }
template <int N>
__device__ __forceinline__ void cp_wait() { asm volatile("cp.async.wait_group %0;" :: "n"(N)); }

// ---------------------------------------------------------------------------
// x -> half conversion (vectorized)
// ---------------------------------------------------------------------------
__global__ __launch_bounds__(256)
void f2h_kernel(const float* __restrict__ X, __half* __restrict__ Xh, int n4) {
    int i = blockIdx.x * blockDim.x + threadIdx.x;
    if (i < n4) {
        float4 v = reinterpret_cast<const float4*>(X)[i];
        reinterpret_cast<__half2*>(Xh)[i * 2]     = __floats2half2_rn(v.x, v.y);
        reinterpret_cast<__half2*>(Xh)[i * 2 + 1] = __floats2half2_rn(v.z, v.w);
    }
}

// ---------------------------------------------------------------------------
// Weight transpose + convert: Wt[n][k] = half(W[k][n]), 512x512
// ---------------------------------------------------------------------------
__global__ __launch_bounds__(256)
void t512h(const float* __restrict__ W, __half* __restrict__ Wt) {
    __shared__ float t[32][33];
    int bx = blockIdx.x * 32, by = blockIdx.y * 32;
    int x = threadIdx.x & 31, y = threadIdx.x >> 5;
#pragma unroll
    for (int i = 0; i < 32; i += 8) t[y + i][x] = W[(size_t)(by + y + i) * 512 + bx + x];
    __syncthreads();
#pragma unroll
    for (int i = 0; i < 32; i += 8)
        Wt[(size_t)(bx + y + i) * 512 + by + x] = __float2half(t[x][y + i]);
}

// ---------------------------------------------------------------------------
// fp16 GEMM: C[M,512] = A[M,512] @ Bt[512,512]^T + bias (opt elu+1)
// A [M][K] half, Bt [N][K] half. Tile 128x128, BK=32, cp.async double buffer.
// 128 threads = 4 warps, warp tile 64x64 (4x8 of m16n8k16).
// HALF_OUT: 1 -> half output, 0 -> float output.
// ---------------------------------------------------------------------------
template <int ACT, int HALF_OUT>
__global__ __launch_bounds__(128, 2)
void gemm_h(const __half* __restrict__ A, const __half* __restrict__ Bt,
            const float* __restrict__ bias, void* __restrict__ Cv)
{
    __shared__ __align__(16) __half As[2][128][40];
    __shared__ __align__(16) __half Bs[2][128][40];

    const int tid = threadIdx.x;
    const int wid = tid >> 5;
    const int lid = tid & 31;
    const int gid = lid >> 2;
    const int tig = lid & 3;
    const int wm  = wid & 1;
    const int wn  = wid >> 1;

    const __half* Ab = A  + (size_t)blockIdx.y * 128 * 512;
    const __half* Bb = Bt + (size_t)blockIdx.x * 128 * 512;

    float acc[4][8][4];
#pragma unroll
    for (int mt = 0; mt < 4; mt++)
#pragma unroll
        for (int nt = 0; nt < 8; nt++)
#pragma unroll
            for (int f = 0; f < 4; f++) acc[mt][nt][f] = 0.f;

    const int crow = tid >> 2;       // 0..31 base row for copies
    const int cc   = tid & 3;        // 16B chunk within 64B row

#define STAGE_COPY(S, BUF)                                                              \
    do {                                                                                \
        _Pragma("unroll")                                                               \
        for (int i = 0; i < 4; i++) {                                                   \
            int row = crow + i * 32;                                                    \
            cp_async16((uint32_t)__cvta_generic_to_shared(&As[BUF][row][cc * 8]),       \
                       Ab + (size_t)row * 512 + (S) * 32 + cc * 8);                     \
            cp_async16((uint32_t)__cvta_generic_to_shared(&Bs[BUF][row][cc * 8]),       \
                       Bb + (size_t)row * 512 + (S) * 32 + cc * 8);                     \
        }                                                                               \
        cp_commit();                                                                    \
    } while (0)

    STAGE_COPY(0, 0);

    for (int s = 0; s < 16; s++) {
        const int buf = s & 1;
        if (s < 15) { STAGE_COPY(s + 1, buf ^ 1); cp_wait<1>(); }
        else        { cp_wait<0>(); }
        __syncthreads();

#pragma unroll
        for (int k16 = 0; k16 < 2; k16++) {
            const int k0 = k16 * 16;
            uint32_t af[4][4];
#pragma unroll
            for (int mt = 0; mt < 4; mt++) {
                int m0 = wm * 64 + mt * 16 + gid;
                af[mt][0] = *reinterpret_cast<const uint32_t*>(&As[buf][m0    ][k0 + tig * 2]);
                af[mt][1] = *reinterpret_cast<const uint32_t*>(&As[buf][m0 + 8][k0 + tig * 2]);
                af[mt][2] = *reinterpret_cast<const uint32_t*>(&As[buf][m0    ][k0 + 8 + tig * 2]);
                af[mt][3] = *reinterpret_cast<const uint32_t*>(&As[buf][m0 + 8][k0 + 8 + tig * 2]);
            }
            uint32_t bf[8][2];
#pragma unroll
            for (int nt = 0; nt < 8; nt++) {
                int n0 = wn * 64 + nt * 8 + gid;
                bf[nt][0] = *reinterpret_cast<const uint32_t*>(&Bs[buf][n0][k0 + tig * 2]);
                bf[nt][1] = *reinterpret_cast<const uint32_t*>(&Bs[buf][n0][k0 + 8 + tig * 2]);
            }
#pragma unroll
            for (int mt = 0; mt < 4; mt++)
#pragma unroll
                for (int nt = 0; nt < 8; nt++)
                    mma_h(acc[mt][nt], af[mt], bf[nt][0], bf[nt][1]);
        }
        __syncthreads();
    }
#undef STAGE_COPY

    // Epilogue
#pragma unroll
    for (int mt = 0; mt < 4; mt++) {
        size_t r0 = (size_t)blockIdx.y * 128 + wm * 64 + mt * 16 + gid;
#pragma unroll
        for (int nt = 0; nt < 8; nt++) {
            int col = blockIdx.x * 128 + wn * 64 + nt * 8 + tig * 2;
            float bb0 = bias[col], bb1 = bias[col + 1];
            float v0 = acc[mt][nt][0] + bb0;
            float v1 = acc[mt][nt][1] + bb1;
            float v2 = acc[mt][nt][2] + bb0;
            float v3 = acc[mt][nt][3] + bb1;
            if (ACT) {
                v0 = (v0 > 0.f) ? v0 + 1.f : __expf(v0);
                v1 = (v1 > 0.f) ? v1 + 1.f : __expf(v1);
                v2 = (v2 > 0.f) ? v2 + 1.f : __expf(v2);
                v3 = (v3 > 0.f) ? v3 + 1.f : __expf(v3);
            }
            if (HALF_OUT) {
                __half* C = (__half*)Cv;
                *reinterpret_cast<__half2*>(&C[r0 * 512 + col])       = __floats2half2_rn(v0, v1);
                *reinterpret_cast<__half2*>(&C[(r0 + 8) * 512 + col]) = __floats2half2_rn(v2, v3);
            } else {
                float* C = (float*)Cv;
                *reinterpret_cast<float2*>(&C[r0 * 512 + col])       = make_float2(v0, v1);
                *reinterpret_cast<float2*>(&C[(r0 + 8) * 512 + col]) = make_float2(v2, v3);
            }
        }
    }
}

// ---------------------------------------------------------------------------
// kv partial kernel (R2 structure, half inputs)
// ---------------------------------------------------------------------------
__global__ __launch_bounds__(256)
void kv_kernel(const __half* __restrict__ K, const __half* __restrict__ V,
               float* __restrict__ KVP, float* __restrict__ KSP)
{
    __shared__ float ks_s[8][64];
    __shared__ float vs_s[8][64];

    const int tid = threadIdx.x;
    const int bh = blockIdx.x;
    const int b = bh >> 3, h = bh & 7;
    const int chunk = blockIdx.y;
    const int s0 = chunk * 512;

    const int m  = tid & 63;
    const int dg = tid >> 6;
    const int d0 = dg * 16;

    float acc[16];
#pragma unroll
    for (int j = 0; j < 16; j++) acc[j] = 0.f;
    float ksacc = 0.f;

    for (int sbk = 0; sbk < 512; sbk += 8) {
#pragma unroll
        for (int i = 0; i < 2; i++) {
            int lin = i * 256 + tid;
            int sr = lin >> 6, dd = lin & 63;
            size_t off = ((size_t)(b * SEQ + s0 + sbk + sr)) * EMB + h * HDIM + dd;
            ks_s[sr][dd] = __half2float(K[off]);
            vs_s[sr][dd] = __half2float(V[off]);
        }
        __syncthreads();
#pragma unroll
        for (int ss = 0; ss < 8; ss++) {
            float vm = vs_s[ss][m];
#pragma unroll
            for (int j = 0; j < 16; j++)
                acc[j] += ks_s[ss][d0 + j] * vm;
        }
        if (tid < 64) {
#pragma unroll
            for (int ss = 0; ss < 8; ss++) ksacc += ks_s[ss][tid];
        }
        __syncthreads();
    }

    float* kvp = KVP + ((size_t)chunk * 64 + bh) * (HDIM * HDIM);
#pragma unroll
    for (int j = 0; j < 16; j++)
        kvp[(d0 + j) * HDIM + m] = acc[j];
    if (tid < 64)
        KSP[((size_t)chunk * 64 + bh) * HDIM + tid] = ksacc;
}

// ---------------------------------------------------------------------------
// Attention via mma: per (b,h), B tile = [kv^T ; ksum ; 0-pad] (72x64),
// o = z * (q @ kv^T) with z = 1/(q . ksum + eps) from MMA column 64.
// grid (64 bh, 32 s-blocks of 128), 256 threads = 8 warps (16 tokens each).
// ---------------------------------------------------------------------------
__global__ __launch_bounds__(256)
void attn_mma(const __half* __restrict__ Q, const float* __restrict__ KVP,
              const float* __restrict__ KSP, __half* __restrict__ O)
{
    __shared__ __align__(16) __half kv_t[72][72];   // [n][k]: n<64 -> kv[m][d], n=64 -> ksum[d]
    __shared__ __align__(16) __half q_s [128][72];

    const int tid = threadIdx.x;
    const int w   = tid >> 5;
    const int lid = tid & 31;
    const int gid = lid >> 2;
    const int tig = lid & 3;
    const int bh = blockIdx.x;
    const int b = bh >> 3, h = bh & 7;
    const int s0 = blockIdx.y * 128;

    // reduce kv partials -> transposed half tile
    for (int i = tid; i < 4096; i += 256) {
        int d = i >> 6, m = i & 63;
        float sum = 0.f;
#pragma unroll
        for (int c = 0; c < NCHUNK; c++)
            sum += KVP[((size_t)(c * 64 + bh)) * 4096 + i];
        kv_t[m][d] = __float2half(sum);
    }
    if (tid < 64) {
        float sum = 0.f;
#pragma unroll
        for (int c = 0; c < NCHUNK; c++)
            sum += KSP[((size_t)(c * 64 + bh)) * HDIM + tid];
        kv_t[64][tid] = __float2half(sum);
    }
    for (int i = tid; i < 7 * 72; i += 256)
        kv_t[65 + i / 72][i % 72] = __float2half(0.f);

    // stage q: 128 tokens x 64 halves
    const __half2* Q2 = reinterpret_cast<const __half2*>(Q + ((size_t)(b * SEQ + s0)) * EMB + h * HDIM);
    for (int i = tid; i < 128 * 32; i += 256) {
        int r = i >> 5, d2 = i & 31;
        *reinterpret_cast<__half2*>(&q_s[r][d2 * 2]) = Q2[(size_t)r * 256 + d2];
    }
    __syncthreads();

    float acc[9][4];
#pragma unroll
    for (int nt = 0; nt < 9; nt++)
#pragma unroll
        for (int f = 0; f < 4; f++) acc[nt][f] = 0.f;

    const int m0 = w * 16;
#pragma unroll
    for (int k16 = 0; k16 < 4; k16++) {
        const int k0 = k16 * 16;
        uint32_t a[4];
        a[0] = *reinterpret_cast<const uint32_t*>(&q_s[m0 + gid    ][k0 + tig * 2]);
        a[1] = *reinterpret_cast<const uint32_t*>(&q_s[m0 + gid + 8][k0 + tig * 2]);
        a[2] = *reinterpret_cast<const uint32_t*>(&q_s[m0 + gid    ][k0 + 8 + tig * 2]);
        a[3] = *reinterpret_cast<const uint32_t*>(&q_s[m0 + gid + 8][k0 + 8 + tig * 2]);
#pragma unroll
        for (int nt = 0; nt < 9; nt++) {
            uint32_t b0 = *reinterpret_cast<const uint32_t*>(&kv_t[nt * 8 + gid][k0 + tig * 2]);
            uint32_t b1 = *reinterpret_cast<const uint32_t*>(&kv_t[nt * 8 + gid][k0 + 8 + tig * 2]);
            mma_h(acc[nt], a, b0, b1);
        }
    }

    // z from MMA column 64 (nt=8, col offset 0 -> held at tig==0), broadcast in row group
    float den0 = __shfl_sync(0xffffffffu, acc[8][0], lid & ~3);
    float den1 = __shfl_sync(0xffffffffu, acc[8][2], lid & ~3);
    float z0 = 1.f / (den0 + 1e-6f);
    float z1 = 1.f / (den1 + 1e-6f);

    size_t row0 = (size_t)(b * SEQ + s0 + m0 + gid);
#pragma unroll
    for (int nt = 0; nt < 8; nt++) {
        int col = h * HDIM + nt * 8 + tig * 2;
        *reinterpret_cast<__half2*>(&O[row0 * EMB + col]) =
            __floats2half2_rn(acc[nt][0] * z0, acc[nt][1] * z0);
        *reinterpret_cast<__half2*>(&O[(row0 + 8) * EMB + col]) =
            __floats2half2_rn(acc[nt][2] * z1, acc[nt][3] * z1);
    }
}

// ---------------------------------------------------------------------------
extern "C" void kernel_launch(void* const* d_in, const int* in_sizes, int n_in,
                              void* d_out, int out_size)
{
    const float* x  = (const float*)d_in[0];
    const float* Wq = (const float*)d_in[1];
    const float* bq = (const float*)d_in[2];
    const float* Wk = (const float*)d_in[3];
    const float* bk = (const float*)d_in[4];
    const float* Wv = (const float*)d_in[5];
    const float* bv = (const float*)d_in[6];
    const float* Wo = (const float*)d_in[7];
    const float* bo = (const float*)d_in[8];
    float* out = (float*)d_out;

    __half *xh, *qh, *kh, *vh, *oh, *wth;
    float *kvp, *ksp;
    cudaGetSymbolAddress((void**)&xh,  g_xh);
    cudaGetSymbolAddress((void**)&qh,  g_qh);
    cudaGetSymbolAddress((void**)&kh,  g_kh);
    cudaGetSymbolAddress((void**)&vh,  g_vh);
    cudaGetSymbolAddress((void**)&oh,  g_oh);
    cudaGetSymbolAddress((void**)&wth, g_wth);
    cudaGetSymbolAddress((void**)&kvp, g_kvp);
    cudaGetSymbolAddress((void**)&ksp, g_ksp);

    __half* wtq = wth;
    __half* wtk = wth + EMB * EMB;
    __half* wtv = wth + 2 * EMB * EMB;
    __half* wto = wth + 3 * EMB * EMB;

    // pre-pass: x -> half, weights -> transposed half
    int n4 = BS_ROWS * EMB / 4;
    f2h_kernel<<<n4 / 256, 256>>>(x, xh, n4);
    dim3 tgrid(16, 16);
    t512h<<<tgrid, 256>>>(Wq, wtq);
    t512h<<<tgrid, 256>>>(Wk, wtk);
    t512h<<<tgrid, 256>>>(Wv, wtv);
    t512h<<<tgrid, 256>>>(Wo, wto);

    dim3 ggrid(4, 256);
    gemm_h<1, 1><<<ggrid, 128>>>(xh, wtq, bq, qh);
    gemm_h<1, 1><<<ggrid, 128>>>(xh, wtk, bk, kh);
    gemm_h<0, 1><<<ggrid, 128>>>(xh, wtv, bv, vh);

    kv_kernel<<<dim3(64, NCHUNK), 256>>>(kh, vh, kvp, ksp);
    attn_mma<<<dim3(64, 32), 256>>>(qh, kvp, ksp, oh);

    gemm_h<0, 0><<<ggrid, 128>>>(oh, wto, bo, out);
}

// round 6
// speedup vs baseline: 4.6626x; 1.2449x over previous
#include <cuda_runtime.h>
#include <cuda_fp16.h>
#include <cstdint>

// Problem constants
#define BATCH 8
#define SEQ   4096
#define EMB   512
#define NHEAD 8
#define HDIM  64
#define BS_ROWS (BATCH*SEQ)          // 32768
#define NCHUNK 8

// Scratch (device globals: allocation-free contract)
__device__ __half g_xh [BS_ROWS * EMB];
__device__ __half g_qh [BS_ROWS * EMB];
__device__ __half g_kt [BS_ROWS * EMB];            // KT[bh][d][s]
__device__ __half g_vt [BS_ROWS * EMB];            // VT[bh][m][s]
__device__ __half g_oh [BS_ROWS * EMB];
__device__ __half g_wth[4 * EMB * EMB];            // transposed half weights [N][K]
__device__ float  g_kvp[NCHUNK * 64 * HDIM * HDIM];// [chunk][bh][d][m]
__device__ float  g_ksp[NCHUNK * 64 * HDIM];       // [chunk][bh][d]
__device__ __half g_kvh[64 * (HDIM * HDIM + HDIM)];// [bh][ m*64+d ; 4096+ksum ]

// ---------------------------------------------------------------------------
// fp16 mma helper (m16n8k16, f32 accumulate)
// ---------------------------------------------------------------------------
__device__ __forceinline__ void mma_h(float* d, const uint32_t* a, uint32_t b0, uint32_t b1) {
    asm volatile(
        "mma.sync.aligned.m16n8k16.row.col.f32.f16.f16.f32 "
        "{%0,%1,%2,%3}, {%4,%5,%6,%7}, {%8,%9}, {%0,%1,%2,%3};"
        : "+f"(d[0]), "+f"(d[1]), "+f"(d[2]), "+f"(d[3])
        : "r"(a[0]), "r"(a[1]), "r"(a[2]), "r"(a[3]), "r"(b0), "r"(b1));
}

__device__ __forceinline__ void cp_async16(uint32_t smem_addr, const void* gptr) {
    asm volatile("cp.async.cg.shared.global [%0], [%1], 16;" :: "r"(smem_addr), "l"(gptr));
}
__device__ __forceinline__ void cp_commit() { asm volatile("cp.async.commit_group;"); }
template <int N>
__device__ __forceinline__ void cp_wait() { asm volatile("cp.async.wait_group %0;" :: "n"(N)); }

// ---------------------------------------------------------------------------
// x -> half conversion
// ---------------------------------------------------------------------------
__global__ __launch_bounds__(256)
void f2h_kernel(const float* __restrict__ X, __half* __restrict__ Xh, int n4) {
    int i = blockIdx.x * blockDim.x + threadIdx.x;
    if (i < n4) {
        float4 v = reinterpret_cast<const float4*>(X)[i];
        reinterpret_cast<__half2*>(Xh)[i * 2]     = __floats2half2_rn(v.x, v.y);
        reinterpret_cast<__half2*>(Xh)[i * 2 + 1] = __floats2half2_rn(v.z, v.w);
    }
}

// ---------------------------------------------------------------------------
// 4 weight transposes in one launch (z selects the matrix)
// ---------------------------------------------------------------------------
__global__ __launch_bounds__(256)
void t512h4(const float* __restrict__ W0, const float* __restrict__ W1,
            const float* __restrict__ W2, const float* __restrict__ W3,
            __half* __restrict__ Wt)
{
    const float* W = (blockIdx.z == 0) ? W0 : (blockIdx.z == 1) ? W1 :
                     (blockIdx.z == 2) ? W2 : W3;
    __half* Wo = Wt + (size_t)blockIdx.z * EMB * EMB;
    __shared__ float t[32][33];
    int bx = blockIdx.x * 32, by = blockIdx.y * 32;
    int x = threadIdx.x & 31, y = threadIdx.x >> 5;
#pragma unroll
    for (int i = 0; i < 32; i += 8) t[y + i][x] = W[(size_t)(by + y + i) * 512 + bx + x];
    __syncthreads();
#pragma unroll
    for (int i = 0; i < 32; i += 8)
        Wo[(size_t)(bx + y + i) * 512 + by + x] = __float2half(t[x][y + i]);
}

// ---------------------------------------------------------------------------
// fp16 GEMM: C[M,512] = A[M,512] @ Bt[512,512]^T + bias (opt elu+1)
// MODE: 0 -> half natural [row][col]; 1 -> half transposed [bh][c][s];
//       2 -> float natural.
// ---------------------------------------------------------------------------
template <int ACT, int MODE>
__global__ __launch_bounds__(128, 2)
void gemm_h(const __half* __restrict__ A, const __half* __restrict__ Bt,
            const float* __restrict__ bias, void* __restrict__ Cv)
{
    __shared__ __align__(16) __half As[2][128][40];
    __shared__ __align__(16) __half Bs[2][128][40];

    const int tid = threadIdx.x;
    const int wid = tid >> 5;
    const int lid = tid & 31;
    const int gid = lid >> 2;
    const int tig = lid & 3;
    const int wm  = wid & 1;
    const int wn  = wid >> 1;

    const __half* Ab = A  + (size_t)blockIdx.y * 128 * 512;
    const __half* Bb = Bt + (size_t)blockIdx.x * 128 * 512;

    float acc[4][8][4];
#pragma unroll
    for (int mt = 0; mt < 4; mt++)
#pragma unroll
        for (int nt = 0; nt < 8; nt++)
#pragma unroll
            for (int f = 0; f < 4; f++) acc[mt][nt][f] = 0.f;

    const int crow = tid >> 2;
    const int cc   = tid & 3;

#define STAGE_COPY(S, BUF)                                                              \
    do {                                                                                \
        _Pragma("unroll")                                                               \
        for (int i = 0; i < 4; i++) {                                                   \
            int row = crow + i * 32;                                                    \
            cp_async16((uint32_t)__cvta_generic_to_shared(&As[BUF][row][cc * 8]),       \
                       Ab + (size_t)row * 512 + (S) * 32 + cc * 8);                     \
            cp_async16((uint32_t)__cvta_generic_to_shared(&Bs[BUF][row][cc * 8]),       \
                       Bb + (size_t)row * 512 + (S) * 32 + cc * 8);                     \
        }                                                                               \
        cp_commit();                                                                    \
    } while (0)

    STAGE_COPY(0, 0);

    for (int s = 0; s < 16; s++) {
        const int buf = s & 1;
        if (s < 15) { STAGE_COPY(s + 1, buf ^ 1); cp_wait<1>(); }
        else        { cp_wait<0>(); }
        __syncthreads();

#pragma unroll
        for (int k16 = 0; k16 < 2; k16++) {
            const int k0 = k16 * 16;
            uint32_t af[4][4];
#pragma unroll
            for (int mt = 0; mt < 4; mt++) {
                int m0 = wm * 64 + mt * 16 + gid;
                af[mt][0] = *reinterpret_cast<const uint32_t*>(&As[buf][m0    ][k0 + tig * 2]);
                af[mt][1] = *reinterpret_cast<const uint32_t*>(&As[buf][m0 + 8][k0 + tig * 2]);
                af[mt][2] = *reinterpret_cast<const uint32_t*>(&As[buf][m0    ][k0 + 8 + tig * 2]);
                af[mt][3] = *reinterpret_cast<const uint32_t*>(&As[buf][m0 + 8][k0 + 8 + tig * 2]);
            }
            uint32_t bf[8][2];
#pragma unroll
            for (int nt = 0; nt < 8; nt++) {
                int n0 = wn * 64 + nt * 8 + gid;
                bf[nt][0] = *reinterpret_cast<const uint32_t*>(&Bs[buf][n0][k0 + tig * 2]);
                bf[nt][1] = *reinterpret_cast<const uint32_t*>(&Bs[buf][n0][k0 + 8 + tig * 2]);
            }
#pragma unroll
            for (int mt = 0; mt < 4; mt++)
#pragma unroll
                for (int nt = 0; nt < 8; nt++)
                    mma_h(acc[mt][nt], af[mt], bf[nt][0], bf[nt][1]);
        }
        __syncthreads();
    }
#undef STAGE_COPY

    // Epilogue
#pragma unroll
    for (int mt = 0; mt < 4; mt++) {
        size_t r0 = (size_t)blockIdx.y * 128 + wm * 64 + mt * 16 + gid;
#pragma unroll
        for (int nt = 0; nt < 8; nt++) {
            int col = blockIdx.x * 128 + wn * 64 + nt * 8 + tig * 2;
            float bb0 = bias[col], bb1 = bias[col + 1];
            float v0 = acc[mt][nt][0] + bb0;
            float v1 = acc[mt][nt][1] + bb1;
            float v2 = acc[mt][nt][2] + bb0;
            float v3 = acc[mt][nt][3] + bb1;
            if (ACT) {
                v0 = (v0 > 0.f) ? v0 + 1.f : __expf(v0);
                v1 = (v1 > 0.f) ? v1 + 1.f : __expf(v1);
                v2 = (v2 > 0.f) ? v2 + 1.f : __expf(v2);
                v3 = (v3 > 0.f) ? v3 + 1.f : __expf(v3);
            }
            if (MODE == 0) {
                __half* C = (__half*)Cv;
                *reinterpret_cast<__half2*>(&C[r0 * 512 + col])       = __floats2half2_rn(v0, v1);
                *reinterpret_cast<__half2*>(&C[(r0 + 8) * 512 + col]) = __floats2half2_rn(v2, v3);
            } else if (MODE == 1) {
                // transposed: out[bh][c][s], c = col&63, h = col>>6, b = r0>>12, s = r0&4095
                __half* C = (__half*)Cv;
                int b = (int)(r0 >> 12), ss = (int)(r0 & 4095);
                int h = col >> 6, d = col & 63;
                size_t base = (((size_t)(b * 8 + h)) * 64 + d) * 4096;
                C[base + ss]            = __float2half(v0);
                C[base + 4096 + ss]     = __float2half(v1);
                C[base + ss + 8]        = __float2half(v2);
                C[base + 4096 + ss + 8] = __float2half(v3);
            } else {
                float* C = (float*)Cv;
                *reinterpret_cast<float2*>(&C[r0 * 512 + col])       = make_float2(v0, v1);
                *reinterpret_cast<float2*>(&C[(r0 + 8) * 512 + col]) = make_float2(v2, v3);
            }
        }
    }
}

// ---------------------------------------------------------------------------
// kv via tensor cores: per (bh, chunk of 512 s):
//   C[d][n] = sum_s KT[d][s] * VTe[n][s], n<64 -> kv[d][m], n=64 -> ksum[d]
// 128 threads = 4 warps; warp w owns d-rows [w*16, w*16+16); N=72 (9 n8 tiles).
// ---------------------------------------------------------------------------
__global__ __launch_bounds__(128)
void kv_mma(const __half* __restrict__ KT, const __half* __restrict__ VT,
            float* __restrict__ KVP, float* __restrict__ KSP)
{
    __shared__ __align__(16) __half kt_s[2][64][72];
    __shared__ __align__(16) __half vt_s[2][72][72];

    const int tid = threadIdx.x;
    const int w = tid >> 5, lid = tid & 31;
    const int gid = lid >> 2, tig = lid & 3;
    const int bh = blockIdx.x, chunk = blockIdx.y;
    const int s0 = chunk * 512;

    // init vt rows 64-71 (row 64 = ones for ksum, rest zero), both buffers
    for (int i = tid; i < 2 * 8 * 72; i += 128) {
        int bufr = i / 72, c = i % 72;
        int buf = bufr >> 3, r = 64 + (bufr & 7);
        vt_s[buf][r][c] = __float2half((r == 64) ? 1.f : 0.f);
    }

    const __half* ktb = KT + (size_t)bh * 64 * 4096 + s0;
    const __half* vtb = VT + (size_t)bh * 64 * 4096 + s0;

    const int crow = tid >> 1;        // 0..63
    const int cc   = (tid & 1) * 4;   // 4 chunks of 16B each

#define KV_COPY(ST, BUF)                                                                  \
    do {                                                                                  \
        _Pragma("unroll")                                                                 \
        for (int i = 0; i < 4; i++) {                                                     \
            cp_async16((uint32_t)__cvta_generic_to_shared(&kt_s[BUF][crow][(cc + i) * 8]),\
                       ktb + (size_t)crow * 4096 + (ST) * 64 + (cc + i) * 8);             \
            cp_async16((uint32_t)__cvta_generic_to_shared(&vt_s[BUF][crow][(cc + i) * 8]),\
                       vtb + (size_t)crow * 4096 + (ST) * 64 + (cc + i) * 8);             \
        }                                                                                 \
        cp_commit();                                                                      \
    } while (0)

    float acc[9][4];
#pragma unroll
    for (int nt = 0; nt < 9; nt++)
#pragma unroll
        for (int f = 0; f < 4; f++) acc[nt][f] = 0.f;

    KV_COPY(0, 0);
    for (int st = 0; st < 8; st++) {
        const int buf = st & 1;
        if (st < 7) { KV_COPY(st + 1, buf ^ 1); cp_wait<1>(); }
        else        { cp_wait<0>(); }
        __syncthreads();

        const int m0 = w * 16;
#pragma unroll
        for (int k16 = 0; k16 < 4; k16++) {
            const int k0 = k16 * 16;
            uint32_t a[4];
            a[0] = *reinterpret_cast<const uint32_t*>(&kt_s[buf][m0 + gid    ][k0 + tig * 2]);
            a[1] = *reinterpret_cast<const uint32_t*>(&kt_s[buf][m0 + gid + 8][k0 + tig * 2]);
            a[2] = *reinterpret_cast<const uint32_t*>(&kt_s[buf][m0 + gid    ][k0 + 8 + tig * 2]);
            a[3] = *reinterpret_cast<const uint32_t*>(&kt_s[buf][m0 + gid + 8][k0 + 8 + tig * 2]);
#pragma unroll
            for (int nt = 0; nt < 9; nt++) {
                uint32_t b0 = *reinterpret_cast<const uint32_t*>(&vt_s[buf][nt * 8 + gid][k0 + tig * 2]);
                uint32_t b1 = *reinterpret_cast<const uint32_t*>(&vt_s[buf][nt * 8 + gid][k0 + 8 + tig * 2]);
                mma_h(acc[nt], a, b0, b1);
            }
        }
        __syncthreads();
    }
#undef KV_COPY

    float* kvp = KVP + ((size_t)chunk * 64 + bh) * 4096;
    const int d0 = w * 16 + gid;
#pragma unroll
    for (int nt = 0; nt < 8; nt++) {
        int m = nt * 8 + tig * 2;
        *reinterpret_cast<float2*>(&kvp[d0 * 64 + m])       = make_float2(acc[nt][0], acc[nt][1]);
        *reinterpret_cast<float2*>(&kvp[(d0 + 8) * 64 + m]) = make_float2(acc[nt][2], acc[nt][3]);
    }
    if (tig == 0) {
        float* ksp = KSP + ((size_t)chunk * 64 + bh) * 64;
        ksp[d0]     = acc[8][0];
        ksp[d0 + 8] = acc[8][2];
    }
}

// ---------------------------------------------------------------------------
// Reduce kv partials over chunks -> half table [bh]{ [m][d] (4096), ksum (64) }
// ---------------------------------------------------------------------------
__global__ __launch_bounds__(256)
void kv_reduce(const float* __restrict__ KVP, const float* __restrict__ KSP,
               __half* __restrict__ KVH)
{
    const int bh = blockIdx.x, tid = threadIdx.x;
    __half* dst = KVH + (size_t)bh * 4160;
    for (int i = tid; i < 4096; i += 256) {
        float s = 0.f;
#pragma unroll
        for (int c = 0; c < NCHUNK; c++)
            s += KVP[((size_t)c * 64 + bh) * 4096 + i];
        int d = i >> 6, m = i & 63;
        dst[m * 64 + d] = __float2half(s);
    }
    if (tid < 64) {
        float s = 0.f;
#pragma unroll
        for (int c = 0; c < NCHUNK; c++)
            s += KSP[((size_t)c * 64 + bh) * 64 + tid];
        dst[4096 + tid] = __float2half(s);
    }
}

// ---------------------------------------------------------------------------
// Attention via mma: B tile rows = [kv[m][d]; ksum[d]; 0-pad] (72x64),
// o = z * (q @ kv^T), z = 1/(q.ksum + eps) from MMA column 64.
// ---------------------------------------------------------------------------
__global__ __launch_bounds__(256)
void attn_mma(const __half* __restrict__ Q, const __half* __restrict__ KVH,
              __half* __restrict__ O)
{
    __shared__ __align__(16) __half kv_t[72][72];
    __shared__ __align__(16) __half q_s [128][72];

    const int tid = threadIdx.x;
    const int w   = tid >> 5;
    const int lid = tid & 31;
    const int gid = lid >> 2;
    const int tig = lid & 3;
    const int bh = blockIdx.x;
    const int b = bh >> 3, h = bh & 7;
    const int s0 = blockIdx.y * 128;

    // load kv table (65 rows x 64 halves = 520 uint4)
    const uint4* kvg = reinterpret_cast<const uint4*>(KVH + (size_t)bh * 4160);
    for (int i = tid; i < 520; i += 256) {
        int m = i >> 3, dc = i & 7;
        *reinterpret_cast<uint4*>(&kv_t[m][dc * 8]) = kvg[i];
    }
    for (int i = tid; i < 7 * 72; i += 256)
        kv_t[65 + i / 72][i % 72] = __float2half(0.f);

    const __half2* Q2 = reinterpret_cast<const __half2*>(Q + ((size_t)(b * SEQ + s0)) * EMB + h * HDIM);
    for (int i = tid; i < 128 * 32; i += 256) {
        int r = i >> 5, d2 = i & 31;
        *reinterpret_cast<__half2*>(&q_s[r][d2 * 2]) = Q2[(size_t)r * 256 + d2];
    }
    __syncthreads();

    float acc[9][4];
#pragma unroll
    for (int nt = 0; nt < 9; nt++)
#pragma unroll
        for (int f = 0; f < 4; f++) acc[nt][f] = 0.f;

    const int m0 = w * 16;
#pragma unroll
    for (int k16 = 0; k16 < 4; k16++) {
        const int k0 = k16 * 16;
        uint32_t a[4];
        a[0] = *reinterpret_cast<const uint32_t*>(&q_s[m0 + gid    ][k0 + tig * 2]);
        a[1] = *reinterpret_cast<const uint32_t*>(&q_s[m0 + gid + 8][k0 + tig * 2]);
        a[2] = *reinterpret_cast<const uint32_t*>(&q_s[m0 + gid    ][k0 + 8 + tig * 2]);
        a[3] = *reinterpret_cast<const uint32_t*>(&q_s[m0 + gid + 8][k0 + 8 + tig * 2]);
#pragma unroll
        for (int nt = 0; nt < 9; nt++) {
            uint32_t b0 = *reinterpret_cast<const uint32_t*>(&kv_t[nt * 8 + gid][k0 + tig * 2]);
            uint32_t b1 = *reinterpret_cast<const uint32_t*>(&kv_t[nt * 8 + gid][k0 + 8 + tig * 2]);
            mma_h(acc[nt], a, b0, b1);
        }
    }

    float den0 = __shfl_sync(0xffffffffu, acc[8][0], lid & ~3);
    float den1 = __shfl_sync(0xffffffffu, acc[8][2], lid & ~3);
    float z0 = 1.f / (den0 + 1e-6f);
    float z1 = 1.f / (den1 + 1e-6f);

    size_t row0 = (size_t)(b * SEQ + s0 + m0 + gid);
#pragma unroll
    for (int nt = 0; nt < 8; nt++) {
        int col = h * HDIM + nt * 8 + tig * 2;
        *reinterpret_cast<__half2*>(&O[row0 * EMB + col]) =
            __floats2half2_rn(acc[nt][0] * z0, acc[nt][1] * z0);
        *reinterpret_cast<__half2*>(&O[(row0 + 8) * EMB + col]) =
            __floats2half2_rn(acc[nt][2] * z1, acc[nt][3] * z1);
    }
}

// ---------------------------------------------------------------------------
extern "C" void kernel_launch(void* const* d_in, const int* in_sizes, int n_in,
                              void* d_out, int out_size)
{
    const float* x  = (const float*)d_in[0];
    const float* Wq = (const float*)d_in[1];
    const float* bq = (const float*)d_in[2];
    const float* Wk = (const float*)d_in[3];
    const float* bk = (const float*)d_in[4];
    const float* Wv = (const float*)d_in[5];
    const float* bv = (const float*)d_in[6];
    const float* Wo = (const float*)d_in[7];
    const float* bo = (const float*)d_in[8];
    float* out = (float*)d_out;

    __half *xh, *qh, *kt, *vt, *oh, *wth, *kvh;
    float *kvp, *ksp;
    cudaGetSymbolAddress((void**)&xh,  g_xh);
    cudaGetSymbolAddress((void**)&qh,  g_qh);
    cudaGetSymbolAddress((void**)&kt,  g_kt);
    cudaGetSymbolAddress((void**)&vt,  g_vt);
    cudaGetSymbolAddress((void**)&oh,  g_oh);
    cudaGetSymbolAddress((void**)&wth, g_wth);
    cudaGetSymbolAddress((void**)&kvh, g_kvh);
    cudaGetSymbolAddress((void**)&kvp, g_kvp);
    cudaGetSymbolAddress((void**)&ksp, g_ksp);

    __half* wtq = wth;
    __half* wtk = wth + EMB * EMB;
    __half* wtv = wth + 2 * EMB * EMB;
    __half* wto = wth + 3 * EMB * EMB;

    int n4 = BS_ROWS * EMB / 4;
    f2h_kernel<<<n4 / 256, 256>>>(x, xh, n4);
    t512h4<<<dim3(16, 16, 4), 256>>>(Wq, Wk, Wv, Wo, wth);

    dim3 ggrid(4, 256);
    gemm_h<1, 0><<<ggrid, 128>>>(xh, wtq, bq, qh);   // Q natural
    gemm_h<1, 1><<<ggrid, 128>>>(xh, wtk, bk, kt);   // K transposed [bh][d][s]
    gemm_h<0, 1><<<ggrid, 128>>>(xh, wtv, bv, vt);   // V transposed [bh][m][s]

    kv_mma<<<dim3(64, NCHUNK), 128>>>(kt, vt, kvp, ksp);
    kv_reduce<<<64, 256>>>(kvp, ksp, kvh);
    attn_mma<<<dim3(64, 32), 256>>>(qh, kvh, oh);

    gemm_h<0, 2><<<ggrid, 128>>>(oh, wto, bo, out);
}

// round 9
// speedup vs baseline: 5.1416x; 1.1027x over previous
#include <cuda_runtime.h>
#include <cuda_fp16.h>
#include <cstdint>

// Problem constants
#define BATCH 8
#define SEQ   4096
#define EMB   512
#define NHEAD 8
#define HDIM  64
#define BS_ROWS (BATCH*SEQ)          // 32768
#define NCHUNK 8

// Scratch (device globals: allocation-free contract)
__device__ __half g_xh [BS_ROWS * EMB];
__device__ __half g_qh [BS_ROWS * EMB];
__device__ __half g_kt [BS_ROWS * EMB];            // KT[bh][d][s]
__device__ __half g_vt [BS_ROWS * EMB];            // VT[bh][m][s]
__device__ __half g_oh [BS_ROWS * EMB];
__device__ __half g_wth[4 * EMB * EMB];            // transposed half weights [N][K]
__device__ float  g_kvp[NCHUNK * 64 * HDIM * HDIM];// [chunk][bh][d][m]
__device__ float  g_ksp[NCHUNK * 64 * HDIM];       // [chunk][bh][d]
__device__ __half g_kvh[64 * (HDIM * HDIM + HDIM)];// [bh][ m*64+d ; 4096+ksum ]

// ---------------------------------------------------------------------------
// PTX helpers
// ---------------------------------------------------------------------------
__device__ __forceinline__ void mma_h(float* d, const uint32_t* a, uint32_t b0, uint32_t b1) {
    asm volatile(
        "mma.sync.aligned.m16n8k16.row.col.f32.f16.f16.f32 "
        "{%0,%1,%2,%3}, {%4,%5,%6,%7}, {%8,%9}, {%0,%1,%2,%3};"
        : "+f"(d[0]), "+f"(d[1]), "+f"(d[2]), "+f"(d[3])
        : "r"(a[0]), "r"(a[1]), "r"(a[2]), "r"(a[3]), "r"(b0), "r"(b1));
}
__device__ __forceinline__ void ldm_x4(uint32_t* r, uint32_t addr) {
    asm volatile("ldmatrix.sync.aligned.m8n8.x4.shared.b16 {%0,%1,%2,%3}, [%4];"
        : "=r"(r[0]), "=r"(r[1]), "=r"(r[2]), "=r"(r[3]) : "r"(addr));
}
__device__ __forceinline__ void cp_async16(uint32_t smem_addr, const void* gptr) {
    asm volatile("cp.async.cg.shared.global [%0], [%1], 16;" :: "r"(smem_addr), "l"(gptr));
}
__device__ __forceinline__ void cp_commit() { asm volatile("cp.async.commit_group;"); }
template <int N>
__device__ __forceinline__ void cp_wait() { asm volatile("cp.async.wait_group %0;" :: "n"(N)); }

#define SWIZ(row, c) ((c) ^ (((row) >> 1) & 3))

// ---------------------------------------------------------------------------
// x -> half conversion
// ---------------------------------------------------------------------------
__global__ __launch_bounds__(256)
void f2h_kernel(const float* __restrict__ X, __half* __restrict__ Xh, int n4) {
    int i = blockIdx.x * blockDim.x + threadIdx.x;
    if (i < n4) {
        float4 v = reinterpret_cast<const float4*>(X)[i];
        reinterpret_cast<__half2*>(Xh)[i * 2]     = __floats2half2_rn(v.x, v.y);
        reinterpret_cast<__half2*>(Xh)[i * 2 + 1] = __floats2half2_rn(v.z, v.w);
    }
}

// ---------------------------------------------------------------------------
// 4 weight transposes in one launch
// ---------------------------------------------------------------------------
__global__ __launch_bounds__(256)
void t512h4(const float* __restrict__ W0, const float* __restrict__ W1,
            const float* __restrict__ W2, const float* __restrict__ W3,
            __half* __restrict__ Wt)
{
    const float* W = (blockIdx.z == 0) ? W0 : (blockIdx.z == 1) ? W1 :
                     (blockIdx.z == 2) ? W2 : W3;
    __half* Wo = Wt + (size_t)blockIdx.z * EMB * EMB;
    __shared__ float t[32][33];
    int bx = blockIdx.x * 32, by = blockIdx.y * 32;
    int x = threadIdx.x & 31, y = threadIdx.x >> 5;
#pragma unroll
    for (int i = 0; i < 32; i += 8) t[y + i][x] = W[(size_t)(by + y + i) * 512 + bx + x];
    __syncthreads();
#pragma unroll
    for (int i = 0; i < 32; i += 8)
        Wo[(size_t)(bx + y + i) * 512 + by + x] = __float2half(t[x][y + i]);
}

// ---------------------------------------------------------------------------
// GEMM mainloop: 128x128 tile, BK=32, 3-stage cp.async, ldmatrix fragments.
// 256 threads = 8 warps (4 m-positions x 2 n-positions), warp tile 32x64.
// Produces acc[2][8][4] (2 m16 tiles x 8 n8 tiles).
// ---------------------------------------------------------------------------
struct SmemTiles {
    __half A[3][128][32];
    __half B[3][128][32];
};

__device__ __forceinline__ void gemm_mainloop(
    const __half* __restrict__ Ab, const __half* __restrict__ Bb,
    SmemTiles* sm, float acc[2][8][4])
{
    const int tid = threadIdx.x;
    const int wid = tid >> 5, lid = tid & 31;
    const int wm = wid & 3, wn = wid >> 2;

    const int crow = tid >> 1;
    const int cc2  = (tid & 1) * 2;

#define ISSUE_STAGE(S, BUF)                                                               \
    do {                                                                                  \
        _Pragma("unroll")                                                                 \
        for (int j = 0; j < 2; j++) {                                                     \
            int c = cc2 + j, sc = SWIZ(crow, c);                                          \
            cp_async16((uint32_t)__cvta_generic_to_shared(&sm->A[BUF][crow][sc * 8]),     \
                       Ab + (size_t)crow * 512 + (S) * 32 + c * 8);                       \
            cp_async16((uint32_t)__cvta_generic_to_shared(&sm->B[BUF][crow][sc * 8]),     \
                       Bb + (size_t)crow * 512 + (S) * 32 + c * 8);                       \
        }                                                                                 \
        cp_commit();                                                                      \
    } while (0)

    ISSUE_STAGE(0, 0);
    ISSUE_STAGE(1, 1);

    const int lr15 = lid & 15;
    const int lhi  = lid >> 4;

    for (int s = 0; s < 16; s++) {
        const int buf = s % 3;
        if (s < 14) cp_wait<1>(); else cp_wait<0>();
        __syncthreads();
        if (s + 2 < 16) ISSUE_STAGE(s + 2, (s + 2) % 3);

#pragma unroll
        for (int k16 = 0; k16 < 2; k16++) {
            const int kc0 = k16 * 2;
            uint32_t a[2][4];
#pragma unroll
            for (int mt = 0; mt < 2; mt++) {
                int row = wm * 32 + mt * 16 + lr15;
                int kc = kc0 + lhi;
                int sc = SWIZ(row, kc);
                ldm_x4(a[mt], (uint32_t)__cvta_generic_to_shared(&sm->A[buf][row][sc * 8]));
            }
            uint32_t bf[4][4];
#pragma unroll
            for (int ng = 0; ng < 4; ng++) {
                int row = wn * 64 + ng * 16 + lr15;
                int kc = kc0 + lhi;
                int sc = SWIZ(row, kc);
                ldm_x4(bf[ng], (uint32_t)__cvta_generic_to_shared(&sm->B[buf][row][sc * 8]));
            }
#pragma unroll
            for (int mt = 0; mt < 2; mt++)
#pragma unroll
                for (int ng = 0; ng < 4; ng++) {
                    mma_h(acc[mt][2 * ng],     a[mt], bf[ng][0], bf[ng][2]);
                    mma_h(acc[mt][2 * ng + 1], a[mt], bf[ng][1], bf[ng][3]);
                }
        }
        __syncthreads();
    }
#undef ISSUE_STAGE
}

// ---------------------------------------------------------------------------
// Fused Q/K/V GEMM: grid (4, 256, 3). z=0 -> Q natural (+act),
// z=1 -> KT transposed (+act), z=2 -> VT transposed (no act).
// ---------------------------------------------------------------------------
__global__ __launch_bounds__(256, 2)
void qkv_gemm(const __half* __restrict__ Xh, const __half* __restrict__ Wth,
              const float* __restrict__ bq, const float* __restrict__ bk,
              const float* __restrict__ bv,
              __half* __restrict__ Qh, __half* __restrict__ KT, __half* __restrict__ VT)
{
    __shared__ __align__(16) SmemTiles sm;
    const int z = blockIdx.z;
    const __half* Ab = Xh + (size_t)blockIdx.y * 128 * 512;
    const __half* Bb = Wth + (size_t)z * EMB * EMB + (size_t)blockIdx.x * 128 * 512;
    const float* bias = (z == 0) ? bq : (z == 1) ? bk : bv;

    float acc[2][8][4];
#pragma unroll
    for (int mt = 0; mt < 2; mt++)
#pragma unroll
        for (int nt = 0; nt < 8; nt++)
#pragma unroll
            for (int f = 0; f < 4; f++) acc[mt][nt][f] = 0.f;

    gemm_mainloop(Ab, Bb, &sm, acc);

    const int tid = threadIdx.x;
    const int wid = tid >> 5, lid = tid & 31;
    const int wm = wid & 3, wn = wid >> 2;
    const int gid = lid >> 2, tig = lid & 3;
    const int act = (z < 2);

#pragma unroll
    for (int mt = 0; mt < 2; mt++) {
        size_t r0 = (size_t)blockIdx.y * 128 + wm * 32 + mt * 16 + gid;
#pragma unroll
        for (int nt = 0; nt < 8; nt++) {
            int col = blockIdx.x * 128 + wn * 64 + nt * 8 + tig * 2;
            float bb0 = bias[col], bb1 = bias[col + 1];
            float v0 = acc[mt][nt][0] + bb0;
            float v1 = acc[mt][nt][1] + bb1;
            float v2 = acc[mt][nt][2] + bb0;
            float v3 = acc[mt][nt][3] + bb1;
            if (act) {
                v0 = (v0 > 0.f) ? v0 + 1.f : __expf(v0);
                v1 = (v1 > 0.f) ? v1 + 1.f : __expf(v1);
                v2 = (v2 > 0.f) ? v2 + 1.f : __expf(v2);
                v3 = (v3 > 0.f) ? v3 + 1.f : __expf(v3);
            }
            if (z == 0) {
                *reinterpret_cast<__half2*>(&Qh[r0 * 512 + col])       = __floats2half2_rn(v0, v1);
                *reinterpret_cast<__half2*>(&Qh[(r0 + 8) * 512 + col]) = __floats2half2_rn(v2, v3);
            } else {
                __half* C = (z == 1) ? KT : VT;
                int b = (int)(r0 >> 12), ss = (int)(r0 & 4095);
                int h = col >> 6, d = col & 63;
                size_t base = (((size_t)(b * 8 + h)) * 64 + d) * 4096;
                C[base + ss]            = __float2half(v0);
                C[base + 4096 + ss]     = __float2half(v1);
                C[base + ss + 8]        = __float2half(v2);
                C[base + 4096 + ss + 8] = __float2half(v3);
            }
        }
    }
}

// ---------------------------------------------------------------------------
// Output GEMM: out[M,512] = oh @ WoT^T + bo (float out)
// ---------------------------------------------------------------------------
__global__ __launch_bounds__(256, 2)
void out_gemm(const __half* __restrict__ Oh, const __half* __restrict__ Wto,
              const float* __restrict__ bias, float* __restrict__ C)
{
    __shared__ __align__(16) SmemTiles sm;
    const __half* Ab = Oh + (size_t)blockIdx.y * 128 * 512;
    const __half* Bb = Wto + (size_t)blockIdx.x * 128 * 512;

    float acc[2][8][4];
#pragma unroll
    for (int mt = 0; mt < 2; mt++)
#pragma unroll
        for (int nt = 0; nt < 8; nt++)
#pragma unroll
            for (int f = 0; f < 4; f++) acc[mt][nt][f] = 0.f;

    gemm_mainloop(Ab, Bb, &sm, acc);

    const int tid = threadIdx.x;
    const int wid = tid >> 5, lid = tid & 31;
    const int wm = wid & 3, wn = wid >> 2;
    const int gid = lid >> 2, tig = lid & 3;

#pragma unroll
    for (int mt = 0; mt < 2; mt++) {
        size_t r0 = (size_t)blockIdx.y * 128 + wm * 32 + mt * 16 + gid;
#pragma unroll
        for (int nt = 0; nt < 8; nt++) {
            int col = blockIdx.x * 128 + wn * 64 + nt * 8 + tig * 2;
            float bb0 = bias[col], bb1 = bias[col + 1];
            *reinterpret_cast<float2*>(&C[r0 * 512 + col]) =
                make_float2(acc[mt][nt][0] + bb0, acc[mt][nt][1] + bb1);
            *reinterpret_cast<float2*>(&C[(r0 + 8) * 512 + col]) =
                make_float2(acc[mt][nt][2] + bb0, acc[mt][nt][3] + bb1);
        }
    }
}

// ---------------------------------------------------------------------------
// kv via tensor cores (unchanged from R6)
// ---------------------------------------------------------------------------
__global__ __launch_bounds__(128)
void kv_mma(const __half* __restrict__ KT, const __half* __restrict__ VT,
            float* __restrict__ KVP, float* __restrict__ KSP)
{
    __shared__ __align__(16) __half kt_s[2][64][72];
    __shared__ __align__(16) __half vt_s[2][72][72];

    const int tid = threadIdx.x;
    const int w = tid >> 5, lid = tid & 31;
    const int gid = lid >> 2, tig = lid & 3;
    const int bh = blockIdx.x, chunk = blockIdx.y;
    const int s0 = chunk * 512;

    for (int i = tid; i < 2 * 8 * 72; i += 128) {
        int bufr = i / 72, c = i % 72;
        int buf = bufr >> 3, r = 64 + (bufr & 7);
        vt_s[buf][r][c] = __float2half((r == 64) ? 1.f : 0.f);
    }

    const __half* ktb = KT + (size_t)bh * 64 * 4096 + s0;
    const __half* vtb = VT + (size_t)bh * 64 * 4096 + s0;

    const int crow = tid >> 1;
    const int cc   = (tid & 1) * 4;

#define KV_COPY(ST, BUF)                                                                  \
    do {                                                                                  \
        _Pragma("unroll")                                                                 \
        for (int i = 0; i < 4; i++) {                                                     \
            cp_async16((uint32_t)__cvta_generic_to_shared(&kt_s[BUF][crow][(cc + i) * 8]),\
                       ktb + (size_t)crow * 4096 + (ST) * 64 + (cc + i) * 8);             \
            cp_async16((uint32_t)__cvta_generic_to_shared(&vt_s[BUF][crow][(cc + i) * 8]),\
                       vtb + (size_t)crow * 4096 + (ST) * 64 + (cc + i) * 8);             \
        }                                                                                 \
        cp_commit();                                                                      \
    } while (0)

    float acc[9][4];
#pragma unroll
    for (int nt = 0; nt < 9; nt++)
#pragma unroll
        for (int f = 0; f < 4; f++) acc[nt][f] = 0.f;

    KV_COPY(0, 0);
    for (int st = 0; st < 8; st++) {
        const int buf = st & 1;
        if (st < 7) { KV_COPY(st + 1, buf ^ 1); cp_wait<1>(); }
        else        { cp_wait<0>(); }
        __syncthreads();

        const int m0 = w * 16;
#pragma unroll
        for (int k16 = 0; k16 < 4; k16++) {
            const int k0 = k16 * 16;
            uint32_t a[4];
            a[0] = *reinterpret_cast<const uint32_t*>(&kt_s[buf][m0 + gid    ][k0 + tig * 2]);
            a[1] = *reinterpret_cast<const uint32_t*>(&kt_s[buf][m0 + gid + 8][k0 + tig * 2]);
            a[2] = *reinterpret_cast<const uint32_t*>(&kt_s[buf][m0 + gid    ][k0 + 8 + tig * 2]);
            a[3] = *reinterpret_cast<const uint32_t*>(&kt_s[buf][m0 + gid + 8][k0 + 8 + tig * 2]);
#pragma unroll
            for (int nt = 0; nt < 9; nt++) {
                uint32_t b0 = *reinterpret_cast<const uint32_t*>(&vt_s[buf][nt * 8 + gid][k0 + tig * 2]);
                uint32_t b1 = *reinterpret_cast<const uint32_t*>(&vt_s[buf][nt * 8 + gid][k0 + 8 + tig * 2]);
                mma_h(acc[nt], a, b0, b1);
            }
        }
        __syncthreads();
    }
#undef KV_COPY

    float* kvp = KVP + ((size_t)chunk * 64 + bh) * 4096;
    const int d0 = w * 16 + gid;
#pragma unroll
    for (int nt = 0; nt < 8; nt++) {
        int m = nt * 8 + tig * 2;
        *reinterpret_cast<float2*>(&kvp[d0 * 64 + m])       = make_float2(acc[nt][0], acc[nt][1]);
        *reinterpret_cast<float2*>(&kvp[(d0 + 8) * 64 + m]) = make_float2(acc[nt][2], acc[nt][3]);
    }
    if (tig == 0) {
        float* ksp = KSP + ((size_t)chunk * 64 + bh) * 64;
        ksp[d0]     = acc[8][0];
        ksp[d0 + 8] = acc[8][2];
    }
}

// ---------------------------------------------------------------------------
// Reduce kv partials -> half table (unchanged from R6)
// ---------------------------------------------------------------------------
__global__ __launch_bounds__(256)
void kv_reduce(const float* __restrict__ KVP, const float* __restrict__ KSP,
               __half* __restrict__ KVH)
{
    const int bh = blockIdx.x, tid = threadIdx.x;
    __half* dst = KVH + (size_t)bh * 4160;
    for (int i = tid; i < 4096; i += 256) {
        float s = 0.f;
#pragma unroll
        for (int c = 0; c < NCHUNK; c++)
            s += KVP[((size_t)c * 64 + bh) * 4096 + i];
        int d = i >> 6, m = i & 63;
        dst[m * 64 + d] = __float2half(s);
    }
    if (tid < 64) {
        float s = 0.f;
#pragma unroll
        for (int c = 0; c < NCHUNK; c++)
            s += KSP[((size_t)c * 64 + bh) * 64 + tid];
        dst[4096 + tid] = __float2half(s);
    }
}

// ---------------------------------------------------------------------------
// Attention via mma (unchanged from R6)
// ---------------------------------------------------------------------------
__global__ __launch_bounds__(256)
void attn_mma(const __half* __restrict__ Q, const __half* __restrict__ KVH,
              __half* __restrict__ O)
{
    __shared__ __align__(16) __half kv_t[72][72];
    __shared__ __align__(16) __half q_s [128][72];

    const int tid = threadIdx.x;
    const int w   = tid >> 5;
    const int lid = tid & 31;
    const int gid = lid >> 2;
    const int tig = lid & 3;
    const int bh = blockIdx.x;
    const int b = bh >> 3, h = bh & 7;
    const int s0 = blockIdx.y * 128;

    const uint4* kvg = reinterpret_cast<const uint4*>(KVH + (size_t)bh * 4160);
    for (int i = tid; i < 520; i += 256) {
        int m = i >> 3, dc = i & 7;
        *reinterpret_cast<uint4*>(&kv_t[m][dc * 8]) = kvg[i];
    }
    for (int i = tid; i < 7 * 72; i += 256)
        kv_t[65 + i / 72][i % 72] = __float2half(0.f);

    const __half2* Q2 = reinterpret_cast<const __half2*>(Q + ((size_t)(b * SEQ + s0)) * EMB + h * HDIM);
    for (int i = tid; i < 128 * 32; i += 256) {
        int r = i >> 5, d2 = i & 31;
        *reinterpret_cast<__half2*>(&q_s[r][d2 * 2]) = Q2[(size_t)r * 256 + d2];
    }
    __syncthreads();

    float acc[9][4];
#pragma unroll
    for (int nt = 0; nt < 9; nt++)
#pragma unroll
        for (int f = 0; f < 4; f++) acc[nt][f] = 0.f;

    const int m0 = w * 16;
#pragma unroll
    for (int k16 = 0; k16 < 4; k16++) {
        const int k0 = k16 * 16;
        uint32_t a[4];
        a[0] = *reinterpret_cast<const uint32_t*>(&q_s[m0 + gid    ][k0 + tig * 2]);
        a[1] = *reinterpret_cast<const uint32_t*>(&q_s[m0 + gid + 8][k0 + tig * 2]);
        a[2] = *reinterpret_cast<const uint32_t*>(&q_s[m0 + gid    ][k0 + 8 + tig * 2]);
        a[3] = *reinterpret_cast<const uint32_t*>(&q_s[m0 + gid + 8][k0 + 8 + tig * 2]);
#pragma unroll
        for (int nt = 0; nt < 9; nt++) {
            uint32_t b0 = *reinterpret_cast<const uint32_t*>(&kv_t[nt * 8 + gid][k0 + tig * 2]);
            uint32_t b1 = *reinterpret_cast<const uint32_t*>(&kv_t[nt * 8 + gid][k0 + 8 + tig * 2]);
            mma_h(acc[nt], a, b0, b1);
        }
    }

    float den0 = __shfl_sync(0xffffffffu, acc[8][0], lid & ~3);
    float den1 = __shfl_sync(0xffffffffu, acc[8][2], lid & ~3);
    float z0 = 1.f / (den0 + 1e-6f);
    float z1 = 1.f / (den1 + 1e-6f);

    size_t row0 = (size_t)(b * SEQ + s0 + m0 + gid);
#pragma unroll
    for (int nt = 0; nt < 8; nt++) {
        int col = h * HDIM + nt * 8 + tig * 2;
        *reinterpret_cast<__half2*>(&O[row0 * EMB + col]) =
            __floats2half2_rn(acc[nt][0] * z0, acc[nt][1] * z0);
        *reinterpret_cast<__half2*>(&O[(row0 + 8) * EMB + col]) =
            __floats2half2_rn(acc[nt][2] * z1, acc[nt][3] * z1);
    }
}

// ---------------------------------------------------------------------------
extern "C" void kernel_launch(void* const* d_in, const int* in_sizes, int n_in,
                              void* d_out, int out_size)
{
    const float* x  = (const float*)d_in[0];
    const float* Wq = (const float*)d_in[1];
    const float* bq = (const float*)d_in[2];
    const float* Wk = (const float*)d_in[3];
    const float* bk = (const float*)d_in[4];
    const float* Wv = (const float*)d_in[5];
    const float* bv = (const float*)d_in[6];
    const float* Wo = (const float*)d_in[7];
    const float* bo = (const float*)d_in[8];
    float* out = (float*)d_out;

    __half *xh, *qh, *kt, *vt, *oh, *wth, *kvh;
    float *kvp, *ksp;
    cudaGetSymbolAddress((void**)&xh,  g_xh);
    cudaGetSymbolAddress((void**)&qh,  g_qh);
    cudaGetSymbolAddress((void**)&kt,  g_kt);
    cudaGetSymbolAddress((void**)&vt,  g_vt);
    cudaGetSymbolAddress((void**)&oh,  g_oh);
    cudaGetSymbolAddress((void**)&wth, g_wth);
    cudaGetSymbolAddress((void**)&kvh, g_kvh);
    cudaGetSymbolAddress((void**)&kvp, g_kvp);
    cudaGetSymbolAddress((void**)&ksp, g_ksp);

    int n4 = BS_ROWS * EMB / 4;
    f2h_kernel<<<n4 / 256, 256>>>(x, xh, n4);
    t512h4<<<dim3(16, 16, 4), 256>>>(Wq, Wk, Wv, Wo, wth);

    qkv_gemm<<<dim3(4, 256, 3), 256>>>(xh, wth, bq, bk, bv, qh, kt, vt);

    kv_mma<<<dim3(64, NCHUNK), 128>>>(kt, vt, kvp, ksp);
    kv_reduce<<<64, 256>>>(kvp, ksp, kvh);
    attn_mma<<<dim3(64, 32), 256>>>(qh, kvh, oh);

    out_gemm<<<dim3(4, 256), 256>>>(oh, wth + 3 * EMB * EMB, bo, out);
}

// round 10
// speedup vs baseline: 5.7332x; 1.1151x over previous
#include <cuda_runtime.h>
#include <cuda_fp16.h>
#include <cstdint>

// Problem constants
#define BATCH 8
#define SEQ   4096
#define EMB   512
#define NHEAD 8
#define HDIM  64
#define BS_ROWS (BATCH*SEQ)          // 32768
#define NCHUNK 16

// Scratch (device globals: allocation-free contract)
__device__ __half g_xh [BS_ROWS * EMB];
__device__ __half g_qh [BS_ROWS * EMB];
__device__ __half g_kt [BS_ROWS * EMB];            // KT[bh][d][s]
__device__ __half g_vt [BS_ROWS * EMB];            // VT[bh][m][s]
__device__ __half g_oh [BS_ROWS * EMB];
__device__ __half g_wth[4 * EMB * EMB];            // transposed half weights [N][K]
__device__ float  g_kvp[NCHUNK * 64 * HDIM * HDIM];// [chunk][bh][d][m]
__device__ float  g_ksp[NCHUNK * 64 * HDIM];       // [chunk][bh][d]
__device__ __half g_kvh[64 * (HDIM * HDIM + HDIM)];// [bh][ m*64+d ; 4096+ksum ]

// ---------------------------------------------------------------------------
// PTX helpers
// ---------------------------------------------------------------------------
__device__ __forceinline__ void mma_h(float* d, const uint32_t* a, uint32_t b0, uint32_t b1) {
    asm volatile(
        "mma.sync.aligned.m16n8k16.row.col.f32.f16.f16.f32 "
        "{%0,%1,%2,%3}, {%4,%5,%6,%7}, {%8,%9}, {%0,%1,%2,%3};"
        : "+f"(d[0]), "+f"(d[1]), "+f"(d[2]), "+f"(d[3])
        : "r"(a[0]), "r"(a[1]), "r"(a[2]), "r"(a[3]), "r"(b0), "r"(b1));
}
__device__ __forceinline__ void ldm_x4(uint32_t* r, uint32_t addr) {
    asm volatile("ldmatrix.sync.aligned.m8n8.x4.shared.b16 {%0,%1,%2,%3}, [%4];"
        : "=r"(r[0]), "=r"(r[1]), "=r"(r[2]), "=r"(r[3]) : "r"(addr));
}
__device__ __forceinline__ void cp_async16(uint32_t smem_addr, const void* gptr) {
    asm volatile("cp.async.cg.shared.global [%0], [%1], 16;" :: "r"(smem_addr), "l"(gptr));
}
__device__ __forceinline__ void cp_commit() { asm volatile("cp.async.commit_group;"); }
template <int N>
__device__ __forceinline__ void cp_wait() { asm volatile("cp.async.wait_group %0;" :: "n"(N)); }

// ---------------------------------------------------------------------------
// x -> half conversion
// ---------------------------------------------------------------------------
__global__ __launch_bounds__(256)
void f2h_kernel(const float* __restrict__ X, __half* __restrict__ Xh, int n4) {
    int i = blockIdx.x * blockDim.x + threadIdx.x;
    if (i < n4) {
        float4 v = reinterpret_cast<const float4*>(X)[i];
        reinterpret_cast<__half2*>(Xh)[i * 2]     = __floats2half2_rn(v.x, v.y);
        reinterpret_cast<__half2*>(Xh)[i * 2 + 1] = __floats2half2_rn(v.z, v.w);
    }
}

// ---------------------------------------------------------------------------
// 4 weight transposes in one launch
// ---------------------------------------------------------------------------
__global__ __launch_bounds__(256)
void t512h4(const float* __restrict__ W0, const float* __restrict__ W1,
            const float* __restrict__ W2, const float* __restrict__ W3,
            __half* __restrict__ Wt)
{
    const float* W = (blockIdx.z == 0) ? W0 : (blockIdx.z == 1) ? W1 :
                     (blockIdx.z == 2) ? W2 : W3;
    __half* Wo = Wt + (size_t)blockIdx.z * EMB * EMB;
    __shared__ float t[32][33];
    int bx = blockIdx.x * 32, by = blockIdx.y * 32;
    int x = threadIdx.x & 31, y = threadIdx.x >> 5;
#pragma unroll
    for (int i = 0; i < 32; i += 8) t[y + i][x] = W[(size_t)(by + y + i) * 512 + bx + x];
    __syncthreads();
#pragma unroll
    for (int i = 0; i < 32; i += 8)
        Wo[(size_t)(bx + y + i) * 512 + by + x] = __float2half(t[x][y + i]);
}

// ---------------------------------------------------------------------------
// GEMM mainloop: 128x128 tile, BK=64, 3-stage cp.async (96KB dynamic smem),
// ldmatrix fragments, 8-chunk XOR swizzle. 256 threads = 8 warps,
// warp tile 32x64. acc[2][8][4].
// ---------------------------------------------------------------------------
#define GEMM_SMEM_BYTES (2 * 3 * 128 * 64 * 2)   // A + B, 3 stages: 98304

__device__ __forceinline__ void gemm_mainloop(
    const __half* __restrict__ Ab, const __half* __restrict__ Bb,
    __half* As, __half* Bs, float acc[2][8][4])
{
    const int tid = threadIdx.x;
    const int wid = tid >> 5, lid = tid & 31;
    const int wm = wid & 3, wn = wid >> 2;

    const int crow = tid >> 3;       // 0..31
    const int cch  = tid & 7;        // chunk 0..7

#define ISSUE_STAGE(S, BUF)                                                               \
    do {                                                                                  \
        _Pragma("unroll")                                                                 \
        for (int i = 0; i < 4; i++) {                                                     \
            int row = crow + i * 32;                                                      \
            int sc = cch ^ (row & 7);                                                     \
            cp_async16((uint32_t)__cvta_generic_to_shared(                                \
                           As + ((size_t)(BUF) * 128 + row) * 64 + sc * 8),               \
                       Ab + (size_t)row * 512 + (S) * 64 + cch * 8);                      \
            cp_async16((uint32_t)__cvta_generic_to_shared(                                \
                           Bs + ((size_t)(BUF) * 128 + row) * 64 + sc * 8),               \
                       Bb + (size_t)row * 512 + (S) * 64 + cch * 8);                      \
        }                                                                                 \
        cp_commit();                                                                      \
    } while (0)

    ISSUE_STAGE(0, 0);
    ISSUE_STAGE(1, 1);

    const int lr15 = lid & 15;
    const int lhi  = lid >> 4;

    for (int s = 0; s < 8; s++) {
        const int buf = s % 3;
        if (s < 6) cp_wait<1>(); else cp_wait<0>();
        __syncthreads();
        if (s + 2 < 8) ISSUE_STAGE(s + 2, (s + 2) % 3);

        const __half* Abuf = As + (size_t)buf * 128 * 64;
        const __half* Bbuf = Bs + (size_t)buf * 128 * 64;

#pragma unroll
        for (int k16 = 0; k16 < 4; k16++) {
            const int kc = k16 * 2 + lhi;
            uint32_t a[2][4];
#pragma unroll
            for (int mt = 0; mt < 2; mt++) {
                int row = wm * 32 + mt * 16 + lr15;
                int sc = kc ^ (row & 7);
                ldm_x4(a[mt], (uint32_t)__cvta_generic_to_shared(
                                  Abuf + (size_t)row * 64 + sc * 8));
            }
            uint32_t bf[4][4];
#pragma unroll
            for (int ng = 0; ng < 4; ng++) {
                int row = wn * 64 + ng * 16 + lr15;
                int sc = kc ^ (row & 7);
                ldm_x4(bf[ng], (uint32_t)__cvta_generic_to_shared(
                                   Bbuf + (size_t)row * 64 + sc * 8));
            }
#pragma unroll
            for (int mt = 0; mt < 2; mt++)
#pragma unroll
                for (int ng = 0; ng < 4; ng++) {
                    mma_h(acc[mt][2 * ng],     a[mt], bf[ng][0], bf[ng][2]);
                    mma_h(acc[mt][2 * ng + 1], a[mt], bf[ng][1], bf[ng][3]);
                }
        }
        __syncthreads();
    }
#undef ISSUE_STAGE
}

// ---------------------------------------------------------------------------
// Fused Q/K/V GEMM: grid (4, 256, 3). z=0 -> Q natural (+act),
// z=1 -> KT transposed (+act), z=2 -> VT transposed (no act).
// ---------------------------------------------------------------------------
__global__ __launch_bounds__(256, 2)
void qkv_gemm(const __half* __restrict__ Xh, const __half* __restrict__ Wth,
              const float* __restrict__ bq, const float* __restrict__ bk,
              const float* __restrict__ bv,
              __half* __restrict__ Qh, __half* __restrict__ KT, __half* __restrict__ VT)
{
    extern __shared__ __align__(16) __half smem[];
    __half* As = smem;
    __half* Bs = smem + 3 * 128 * 64;

    const int z = blockIdx.z;
    const __half* Ab = Xh + (size_t)blockIdx.y * 128 * 512;
    const __half* Bb = Wth + (size_t)z * EMB * EMB + (size_t)blockIdx.x * 128 * 512;
    const float* bias = (z == 0) ? bq : (z == 1) ? bk : bv;

    float acc[2][8][4];
#pragma unroll
    for (int mt = 0; mt < 2; mt++)
#pragma unroll
        for (int nt = 0; nt < 8; nt++)
#pragma unroll
            for (int f = 0; f < 4; f++) acc[mt][nt][f] = 0.f;

    gemm_mainloop(Ab, Bb, As, Bs, acc);

    const int tid = threadIdx.x;
    const int wid = tid >> 5, lid = tid & 31;
    const int wm = wid & 3, wn = wid >> 2;
    const int gid = lid >> 2, tig = lid & 3;
    const int act = (z < 2);

#pragma unroll
    for (int mt = 0; mt < 2; mt++) {
        size_t r0 = (size_t)blockIdx.y * 128 + wm * 32 + mt * 16 + gid;
#pragma unroll
        for (int nt = 0; nt < 8; nt++) {
            int col = blockIdx.x * 128 + wn * 64 + nt * 8 + tig * 2;
            float bb0 = bias[col], bb1 = bias[col + 1];
            float v0 = acc[mt][nt][0] + bb0;
            float v1 = acc[mt][nt][1] + bb1;
            float v2 = acc[mt][nt][2] + bb0;
            float v3 = acc[mt][nt][3] + bb1;
            if (act) {
                v0 = (v0 > 0.f) ? v0 + 1.f : __expf(v0);
                v1 = (v1 > 0.f) ? v1 + 1.f : __expf(v1);
                v2 = (v2 > 0.f) ? v2 + 1.f : __expf(v2);
                v3 = (v3 > 0.f) ? v3 + 1.f : __expf(v3);
            }
            if (z == 0) {
                *reinterpret_cast<__half2*>(&Qh[r0 * 512 + col])       = __floats2half2_rn(v0, v1);
                *reinterpret_cast<__half2*>(&Qh[(r0 + 8) * 512 + col]) = __floats2half2_rn(v2, v3);
            } else {
                __half* C = (z == 1) ? KT : VT;
                int b = (int)(r0 >> 12), ss = (int)(r0 & 4095);
                int h = col >> 6, d = col & 63;
                size_t base = (((size_t)(b * 8 + h)) * 64 + d) * 4096;
                C[base + ss]            = __float2half(v0);
                C[base + 4096 + ss]     = __float2half(v1);
                C[base + ss + 8]        = __float2half(v2);
                C[base + 4096 + ss + 8] = __float2half(v3);
            }
        }
    }
}

// ---------------------------------------------------------------------------
// Output GEMM: out[M,512] = oh @ WoT^T + bo (float out)
// ---------------------------------------------------------------------------
__global__ __launch_bounds__(256, 2)
void out_gemm(const __half* __restrict__ Oh, const __half* __restrict__ Wto,
              const float* __restrict__ bias, float* __restrict__ C)
{
    extern __shared__ __align__(16) __half smem[];
    __half* As = smem;
    __half* Bs = smem + 3 * 128 * 64;

    const __half* Ab = Oh + (size_t)blockIdx.y * 128 * 512;
    const __half* Bb = Wto + (size_t)blockIdx.x * 128 * 512;

    float acc[2][8][4];
#pragma unroll
    for (int mt = 0; mt < 2; mt++)
#pragma unroll
        for (int nt = 0; nt < 8; nt++)
#pragma unroll
            for (int f = 0; f < 4; f++) acc[mt][nt][f] = 0.f;

    gemm_mainloop(Ab, Bb, As, Bs, acc);

    const int tid = threadIdx.x;
    const int wid = tid >> 5, lid = tid & 31;
    const int wm = wid & 3, wn = wid >> 2;
    const int gid = lid >> 2, tig = lid & 3;

#pragma unroll
    for (int mt = 0; mt < 2; mt++) {
        size_t r0 = (size_t)blockIdx.y * 128 + wm * 32 + mt * 16 + gid;
#pragma unroll
        for (int nt = 0; nt < 8; nt++) {
            int col = blockIdx.x * 128 + wn * 64 + nt * 8 + tig * 2;
            float bb0 = bias[col], bb1 = bias[col + 1];
            *reinterpret_cast<float2*>(&C[r0 * 512 + col]) =
                make_float2(acc[mt][nt][0] + bb0, acc[mt][nt][1] + bb1);
            *reinterpret_cast<float2*>(&C[(r0 + 8) * 512 + col]) =
                make_float2(acc[mt][nt][2] + bb0, acc[mt][nt][3] + bb1);
        }
    }
}

// ---------------------------------------------------------------------------
// kv via tensor cores: per (bh, chunk of 256 s):
//   C[d][n] = sum_s KT[d][s] * VTe[n][s], n<64 -> kv[d][m], n=64 -> ksum[d]
// ---------------------------------------------------------------------------
__global__ __launch_bounds__(128)
void kv_mma(const __half* __restrict__ KT, const __half* __restrict__ VT,
            float* __restrict__ KVP, float* __restrict__ KSP)
{
    __shared__ __align__(16) __half kt_s[2][64][72];
    __shared__ __align__(16) __half vt_s[2][72][72];

    const int tid = threadIdx.x;
    const int w = tid >> 5, lid = tid & 31;
    const int gid = lid >> 2, tig = lid & 3;
    const int bh = blockIdx.x, chunk = blockIdx.y;
    const int s0 = chunk * 256;

    for (int i = tid; i < 2 * 8 * 72; i += 128) {
        int bufr = i / 72, c = i % 72;
        int buf = bufr >> 3, r = 64 + (bufr & 7);
        vt_s[buf][r][c] = __float2half((r == 64) ? 1.f : 0.f);
    }

    const __half* ktb = KT + (size_t)bh * 64 * 4096 + s0;
    const __half* vtb = VT + (size_t)bh * 64 * 4096 + s0;

    const int crow = tid >> 1;
    const int cc   = (tid & 1) * 4;

#define KV_COPY(ST, BUF)                                                                  \
    do {                                                                                  \
        _Pragma("unroll")                                                                 \
        for (int i = 0; i < 4; i++) {                                                     \
            cp_async16((uint32_t)__cvta_generic_to_shared(&kt_s[BUF][crow][(cc + i) * 8]),\
                       ktb + (size_t)crow * 4096 + (ST) * 64 + (cc + i) * 8);             \
            cp_async16((uint32_t)__cvta_generic_to_shared(&vt_s[BUF][crow][(cc + i) * 8]),\
                       vtb + (size_t)crow * 4096 + (ST) * 64 + (cc + i) * 8);             \
        }                                                                                 \
        cp_commit();                                                                      \
    } while (0)

    float acc[9][4];
#pragma unroll
    for (int nt = 0; nt < 9; nt++)
#pragma unroll
        for (int f = 0; f < 4; f++) acc[nt][f] = 0.f;

    KV_COPY(0, 0);
    for (int st = 0; st < 4; st++) {
        const int buf = st & 1;
        if (st < 3) { KV_COPY(st + 1, buf ^ 1); cp_wait<1>(); }
        else        { cp_wait<0>(); }
        __syncthreads();

        const int m0 = w * 16;
#pragma unroll
        for (int k16 = 0; k16 < 4; k16++) {
            const int k0 = k16 * 16;
            uint32_t a[4];
            a[0] = *reinterpret_cast<const uint32_t*>(&kt_s[buf][m0 + gid    ][k0 + tig * 2]);
            a[1] = *reinterpret_cast<const uint32_t*>(&kt_s[buf][m0 + gid + 8][k0 + tig * 2]);
            a[2] = *reinterpret_cast<const uint32_t*>(&kt_s[buf][m0 + gid    ][k0 + 8 + tig * 2]);
            a[3] = *reinterpret_cast<const uint32_t*>(&kt_s[buf][m0 + gid + 8][k0 + 8 + tig * 2]);
#pragma unroll
            for (int nt = 0; nt < 9; nt++) {
                uint32_t b0 = *reinterpret_cast<const uint32_t*>(&vt_s[buf][nt * 8 + gid][k0 + tig * 2]);
                uint32_t b1 = *reinterpret_cast<const uint32_t*>(&vt_s[buf][nt * 8 + gid][k0 + 8 + tig * 2]);
                mma_h(acc[nt], a, b0, b1);
            }
        }
        __syncthreads();
    }
#undef KV_COPY

    float* kvp = KVP + ((size_t)chunk * 64 + bh) * 4096;
    const int d0 = w * 16 + gid;
#pragma unroll
    for (int nt = 0; nt < 8; nt++) {
        int m = nt * 8 + tig * 2;
        *reinterpret_cast<float2*>(&kvp[d0 * 64 + m])       = make_float2(acc[nt][0], acc[nt][1]);
        *reinterpret_cast<float2*>(&kvp[(d0 + 8) * 64 + m]) = make_float2(acc[nt][2], acc[nt][3]);
    }
    if (tig == 0) {
        float* ksp = KSP + ((size_t)chunk * 64 + bh) * 64;
        ksp[d0]     = acc[8][0];
        ksp[d0 + 8] = acc[8][2];
    }
}

// ---------------------------------------------------------------------------
// Reduce kv partials -> half table
// ---------------------------------------------------------------------------
__global__ __launch_bounds__(256)
void kv_reduce(const float* __restrict__ KVP, const float* __restrict__ KSP,
               __half* __restrict__ KVH)
{
    const int bh = blockIdx.x, tid = threadIdx.x;
    __half* dst = KVH + (size_t)bh * 4160;
    for (int i = tid; i < 4096; i += 256) {
        float s = 0.f;
#pragma unroll
        for (int c = 0; c < NCHUNK; c++)
            s += KVP[((size_t)c * 64 + bh) * 4096 + i];
        int d = i >> 6, m = i & 63;
        dst[m * 64 + d] = __float2half(s);
    }
    if (tid < 64) {
        float s = 0.f;
#pragma unroll
        for (int c = 0; c < NCHUNK; c++)
            s += KSP[((size_t)c * 64 + bh) * 64 + tid];
        dst[4096 + tid] = __float2half(s);
    }
}

// ---------------------------------------------------------------------------
// Attention via mma
// ---------------------------------------------------------------------------
__global__ __launch_bounds__(256)
void attn_mma(const __half* __restrict__ Q, const __half* __restrict__ KVH,
              __half* __restrict__ O)
{
    __shared__ __align__(16) __half kv_t[72][72];
    __shared__ __align__(16) __half q_s [128][72];

    const int tid = threadIdx.x;
    const int w   = tid >> 5;
    const int lid = tid & 31;
    const int gid = lid >> 2;
    const int tig = lid & 3;
    const int bh = blockIdx.x;
    const int b = bh >> 3, h = bh & 7;
    const int s0 = blockIdx.y * 128;

    const uint4* kvg = reinterpret_cast<const uint4*>(KVH + (size_t)bh * 4160);
    for (int i = tid; i < 520; i += 256) {
        int m = i >> 3, dc = i & 7;
        *reinterpret_cast<uint4*>(&kv_t[m][dc * 8]) = kvg[i];
    }
    for (int i = tid; i < 7 * 72; i += 256)
        kv_t[65 + i / 72][i % 72] = __float2half(0.f);

    const __half2* Q2 = reinterpret_cast<const __half2*>(Q + ((size_t)(b * SEQ + s0)) * EMB + h * HDIM);
    for (int i = tid; i < 128 * 32; i += 256) {
        int r = i >> 5, d2 = i & 31;
        *reinterpret_cast<__half2*>(&q_s[r][d2 * 2]) = Q2[(size_t)r * 256 + d2];
    }
    __syncthreads();

    float acc[9][4];
#pragma unroll
    for (int nt = 0; nt < 9; nt++)
#pragma unroll
        for (int f = 0; f < 4; f++) acc[nt][f] = 0.f;

    const int m0 = w * 16;
#pragma unroll
    for (int k16 = 0; k16 < 4; k16++) {
        const int k0 = k16 * 16;
        uint32_t a[4];
        a[0] = *reinterpret_cast<const uint32_t*>(&q_s[m0 + gid    ][k0 + tig * 2]);
        a[1] = *reinterpret_cast<const uint32_t*>(&q_s[m0 + gid + 8][k0 + tig * 2]);
        a[2] = *reinterpret_cast<const uint32_t*>(&q_s[m0 + gid    ][k0 + 8 + tig * 2]);
        a[3] = *reinterpret_cast<const uint32_t*>(&q_s[m0 + gid + 8][k0 + 8 + tig * 2]);
#pragma unroll
        for (int nt = 0; nt < 9; nt++) {
            uint32_t b0 = *reinterpret_cast<const uint32_t*>(&kv_t[nt * 8 + gid][k0 + tig * 2]);
            uint32_t b1 = *reinterpret_cast<const uint32_t*>(&kv_t[nt * 8 + gid][k0 + 8 + tig * 2]);
            mma_h(acc[nt], a, b0, b1);
        }
    }

    float den0 = __shfl_sync(0xffffffffu, acc[8][0], lid & ~3);
    float den1 = __shfl_sync(0xffffffffu, acc[8][2], lid & ~3);
    float z0 = 1.f / (den0 + 1e-6f);
    float z1 = 1.f / (den1 + 1e-6f);

    size_t row0 = (size_t)(b * SEQ + s0 + m0 + gid);
#pragma unroll
    for (int nt = 0; nt < 8; nt++) {
        int col = h * HDIM + nt * 8 + tig * 2;
        *reinterpret_cast<__half2*>(&O[row0 * EMB + col]) =
            __floats2half2_rn(acc[nt][0] * z0, acc[nt][1] * z0);
        *reinterpret_cast<__half2*>(&O[(row0 + 8) * EMB + col]) =
            __floats2half2_rn(acc[nt][2] * z1, acc[nt][3] * z1);
    }
}

// ---------------------------------------------------------------------------
extern "C" void kernel_launch(void* const* d_in, const int* in_sizes, int n_in,
                              void* d_out, int out_size)
{
    const float* x  = (const float*)d_in[0];
    const float* Wq = (const float*)d_in[1];
    const float* bq = (const float*)d_in[2];
    const float* Wk = (const float*)d_in[3];
    const float* bk = (const float*)d_in[4];
    const float* Wv = (const float*)d_in[5];
    const float* bv = (const float*)d_in[6];
    const float* Wo = (const float*)d_in[7];
    const float* bo = (const float*)d_in[8];
    float* out = (float*)d_out;

    __half *xh, *qh, *kt, *vt, *oh, *wth, *kvh;
    float *kvp, *ksp;
    cudaGetSymbolAddress((void**)&xh,  g_xh);
    cudaGetSymbolAddress((void**)&qh,  g_qh);
    cudaGetSymbolAddress((void**)&kt,  g_kt);
    cudaGetSymbolAddress((void**)&vt,  g_vt);
    cudaGetSymbolAddress((void**)&oh,  g_oh);
    cudaGetSymbolAddress((void**)&wth, g_wth);
    cudaGetSymbolAddress((void**)&kvh, g_kvh);
    cudaGetSymbolAddress((void**)&kvp, g_kvp);
    cudaGetSymbolAddress((void**)&ksp, g_ksp);

    cudaFuncSetAttribute(qkv_gemm, cudaFuncAttributeMaxDynamicSharedMemorySize, GEMM_SMEM_BYTES);
    cudaFuncSetAttribute(out_gemm, cudaFuncAttributeMaxDynamicSharedMemorySize, GEMM_SMEM_BYTES);

    int n4 = BS_ROWS * EMB / 4;
    f2h_kernel<<<n4 / 256, 256>>>(x, xh, n4);
    t512h4<<<dim3(16, 16, 4), 256>>>(Wq, Wk, Wv, Wo, wth);

    qkv_gemm<<<dim3(4, 256, 3), 256, GEMM_SMEM_BYTES>>>(xh, wth, bq, bk, bv, qh, kt, vt);

    kv_mma<<<dim3(64, NCHUNK), 128>>>(kt, vt, kvp, ksp);
    kv_reduce<<<64, 256>>>(kvp, ksp, kvh);
    attn_mma<<<dim3(64, 32), 256>>>(qh, kvh, oh);

    out_gemm<<<dim3(4, 256), 256, GEMM_SMEM_BYTES>>>(oh, wth + 3 * EMB * EMB, bo, out);
}

// round 11
// speedup vs baseline: 6.1118x; 1.0660x over previous
#include <cuda_runtime.h>
#include <cuda_fp16.h>
#include <cstdint>

// Problem constants
#define BATCH 8
#define SEQ   4096
#define EMB   512
#define NHEAD 8
#define HDIM  64
#define BS_ROWS (BATCH*SEQ)          // 32768
#define NCHUNK 16

// Scratch (device globals: allocation-free contract)
__device__ __half g_xh [BS_ROWS * EMB];
__device__ __half g_qh [BS_ROWS * EMB];
__device__ __half g_kt [BS_ROWS * EMB];            // KT[bh][d][s]
__device__ __half g_vt [BS_ROWS * EMB];            // VT[bh][m][s]
__device__ __half g_oh [BS_ROWS * EMB];
__device__ __half g_wth[4 * EMB * EMB];            // transposed half weights [N][K]
__device__ float  g_kvp[NCHUNK * 64 * HDIM * HDIM];// [chunk][bh][d][m]
__device__ float  g_ksp[NCHUNK * 64 * HDIM];       // [chunk][bh][d]
__device__ __half g_kvh[64 * (HDIM * HDIM + HDIM)];// [bh][ m*64+d ; 4096+ksum ]

// ---------------------------------------------------------------------------
// PTX helpers
// ---------------------------------------------------------------------------
__device__ __forceinline__ void mma_h(float* d, const uint32_t* a, uint32_t b0, uint32_t b1) {
    asm volatile(
        "mma.sync.aligned.m16n8k16.row.col.f32.f16.f16.f32 "
        "{%0,%1,%2,%3}, {%4,%5,%6,%7}, {%8,%9}, {%0,%1,%2,%3};"
        : "+f"(d[0]), "+f"(d[1]), "+f"(d[2]), "+f"(d[3])
        : "r"(a[0]), "r"(a[1]), "r"(a[2]), "r"(a[3]), "r"(b0), "r"(b1));
}
__device__ __forceinline__ void ldm_x4(uint32_t* r, uint32_t addr) {
    asm volatile("ldmatrix.sync.aligned.m8n8.x4.shared.b16 {%0,%1,%2,%3}, [%4];"
        : "=r"(r[0]), "=r"(r[1]), "=r"(r[2]), "=r"(r[3]) : "r"(addr));
}
__device__ __forceinline__ void cp_async16(uint32_t smem_addr, const void* gptr) {
    asm volatile("cp.async.cg.shared.global [%0], [%1], 16;" :: "r"(smem_addr), "l"(gptr));
}
__device__ __forceinline__ void cp_commit() { asm volatile("cp.async.commit_group;"); }
template <int N>
__device__ __forceinline__ void cp_wait() { asm volatile("cp.async.wait_group %0;" :: "n"(N)); }

// ---------------------------------------------------------------------------
// x -> half conversion
// ---------------------------------------------------------------------------
__global__ __launch_bounds__(256)
void f2h_kernel(const float* __restrict__ X, __half* __restrict__ Xh, int n4) {
    int i = blockIdx.x * blockDim.x + threadIdx.x;
    if (i < n4) {
        float4 v = reinterpret_cast<const float4*>(X)[i];
        reinterpret_cast<__half2*>(Xh)[i * 2]     = __floats2half2_rn(v.x, v.y);
        reinterpret_cast<__half2*>(Xh)[i * 2 + 1] = __floats2half2_rn(v.z, v.w);
    }
}

// ---------------------------------------------------------------------------
// 4 weight transposes in one launch
// ---------------------------------------------------------------------------
__global__ __launch_bounds__(256)
void t512h4(const float* __restrict__ W0, const float* __restrict__ W1,
            const float* __restrict__ W2, const float* __restrict__ W3,
            __half* __restrict__ Wt)
{
    const float* W = (blockIdx.z == 0) ? W0 : (blockIdx.z == 1) ? W1 :
                     (blockIdx.z == 2) ? W2 : W3;
    __half* Wo = Wt + (size_t)blockIdx.z * EMB * EMB;
    __shared__ float t[32][33];
    int bx = blockIdx.x * 32, by = blockIdx.y * 32;
    int x = threadIdx.x & 31, y = threadIdx.x >> 5;
#pragma unroll
    for (int i = 0; i < 32; i += 8) t[y + i][x] = W[(size_t)(by + y + i) * 512 + bx + x];
    __syncthreads();
#pragma unroll
    for (int i = 0; i < 32; i += 8)
        Wo[(size_t)(bx + y + i) * 512 + by + x] = __float2half(t[x][y + i]);
}

// ---------------------------------------------------------------------------
// GEMM mainloop: 128x128 tile, BK=64, 3-stage cp.async (96KB dynamic smem),
// ldmatrix fragments, 8-chunk XOR swizzle, ONE barrier per stage.
// 256 threads = 8 warps, warp tile 32x64. acc[2][8][4].
// ---------------------------------------------------------------------------
#define GEMM_SMEM_BYTES (2 * 3 * 128 * 64 * 2)   // A + B, 3 stages: 98304

__device__ __forceinline__ void gemm_mainloop(
    const __half* __restrict__ Ab, const __half* __restrict__ Bb,
    __half* As, __half* Bs, float acc[2][8][4])
{
    const int tid = threadIdx.x;
    const int wid = tid >> 5, lid = tid & 31;
    const int wm = wid & 3, wn = wid >> 2;

    const int crow = tid >> 3;       // 0..31
    const int cch  = tid & 7;        // chunk 0..7

#define ISSUE_STAGE(S, BUF)                                                               \
    do {                                                                                  \
        _Pragma("unroll")                                                                 \
        for (int i = 0; i < 4; i++) {                                                     \
            int row = crow + i * 32;                                                      \
            int sc = cch ^ (row & 7);                                                     \
            cp_async16((uint32_t)__cvta_generic_to_shared(                                \
                           As + ((size_t)(BUF) * 128 + row) * 64 + sc * 8),               \
                       Ab + (size_t)row * 512 + (S) * 64 + cch * 8);                      \
            cp_async16((uint32_t)__cvta_generic_to_shared(                                \
                           Bs + ((size_t)(BUF) * 128 + row) * 64 + sc * 8),               \
                       Bb + (size_t)row * 512 + (S) * 64 + cch * 8);                      \
        }                                                                                 \
        cp_commit();                                                                      \
    } while (0)

    ISSUE_STAGE(0, 0);
    ISSUE_STAGE(1, 1);

    const int lr15 = lid & 15;
    const int lhi  = lid >> 4;

    for (int s = 0; s < 8; s++) {
        const int buf = s % 3;
        if (s < 6) cp_wait<1>(); else cp_wait<0>();
        // Single barrier per stage: once all warps arrive here, every warp
        // has consumed its stage s-1 fragments (MMA register deps), so the
        // ISSUE_STAGE below (writing buffer (s+2)%3 == (s-1)%3) cannot race.
        __syncthreads();
        if (s + 2 < 8) ISSUE_STAGE(s + 2, (s + 2) % 3);

        const __half* Abuf = As + (size_t)buf * 128 * 64;
        const __half* Bbuf = Bs + (size_t)buf * 128 * 64;

#pragma unroll
        for (int k16 = 0; k16 < 4; k16++) {
            const int kc = k16 * 2 + lhi;
            uint32_t a[2][4];
#pragma unroll
            for (int mt = 0; mt < 2; mt++) {
                int row = wm * 32 + mt * 16 + lr15;
                int sc = kc ^ (row & 7);
                ldm_x4(a[mt], (uint32_t)__cvta_generic_to_shared(
                                  Abuf + (size_t)row * 64 + sc * 8));
            }
            uint32_t bf[4][4];
#pragma unroll
            for (int ng = 0; ng < 4; ng++) {
                int row = wn * 64 + ng * 16 + lr15;
                int sc = kc ^ (row & 7);
                ldm_x4(bf[ng], (uint32_t)__cvta_generic_to_shared(
                                   Bbuf + (size_t)row * 64 + sc * 8));
            }
#pragma unroll
            for (int mt = 0; mt < 2; mt++)
#pragma unroll
                for (int ng = 0; ng < 4; ng++) {
                    mma_h(acc[mt][2 * ng],     a[mt], bf[ng][0], bf[ng][2]);
                    mma_h(acc[mt][2 * ng + 1], a[mt], bf[ng][1], bf[ng][3]);
                }
        }
    }
#undef ISSUE_STAGE
}

// ---------------------------------------------------------------------------
// Fused Q/K/V GEMM: grid (4, 256, 3). z=0 -> Q natural (+act),
// z=1 -> KT transposed (+act), z=2 -> VT transposed (no act).
// ---------------------------------------------------------------------------
__global__ __launch_bounds__(256, 2)
void qkv_gemm(const __half* __restrict__ Xh, const __half* __restrict__ Wth,
              const float* __restrict__ bq, const float* __restrict__ bk,
              const float* __restrict__ bv,
              __half* __restrict__ Qh, __half* __restrict__ KT, __half* __restrict__ VT)
{
    extern __shared__ __align__(16) __half smem[];
    __half* As = smem;
    __half* Bs = smem + 3 * 128 * 64;

    const int z = blockIdx.z;
    const __half* Ab = Xh + (size_t)blockIdx.y * 128 * 512;
    const __half* Bb = Wth + (size_t)z * EMB * EMB + (size_t)blockIdx.x * 128 * 512;
    const float* bias = (z == 0) ? bq : (z == 1) ? bk : bv;

    float acc[2][8][4];
#pragma unroll
    for (int mt = 0; mt < 2; mt++)
#pragma unroll
        for (int nt = 0; nt < 8; nt++)
#pragma unroll
            for (int f = 0; f < 4; f++) acc[mt][nt][f] = 0.f;

    gemm_mainloop(Ab, Bb, As, Bs, acc);

    const int tid = threadIdx.x;
    const int wid = tid >> 5, lid = tid & 31;
    const int wm = wid & 3, wn = wid >> 2;
    const int gid = lid >> 2, tig = lid & 3;
    const int act = (z < 2);

#pragma unroll
    for (int mt = 0; mt < 2; mt++) {
        size_t r0 = (size_t)blockIdx.y * 128 + wm * 32 + mt * 16 + gid;
#pragma unroll
        for (int nt = 0; nt < 8; nt++) {
            int col = blockIdx.x * 128 + wn * 64 + nt * 8 + tig * 2;
            float bb0 = bias[col], bb1 = bias[col + 1];
            float v0 = acc[mt][nt][0] + bb0;
            float v1 = acc[mt][nt][1] + bb1;
            float v2 = acc[mt][nt][2] + bb0;
            float v3 = acc[mt][nt][3] + bb1;
            if (act) {
                v0 = (v0 > 0.f) ? v0 + 1.f : __expf(v0);
                v1 = (v1 > 0.f) ? v1 + 1.f : __expf(v1);
                v2 = (v2 > 0.f) ? v2 + 1.f : __expf(v2);
                v3 = (v3 > 0.f) ? v3 + 1.f : __expf(v3);
            }
            if (z == 0) {
                *reinterpret_cast<__half2*>(&Qh[r0 * 512 + col])       = __floats2half2_rn(v0, v1);
                *reinterpret_cast<__half2*>(&Qh[(r0 + 8) * 512 + col]) = __floats2half2_rn(v2, v3);
            } else {
                __half* C = (z == 1) ? KT : VT;
                int b = (int)(r0 >> 12), ss = (int)(r0 & 4095);
                int h = col >> 6, d = col & 63;
                size_t base = (((size_t)(b * 8 + h)) * 64 + d) * 4096;
                C[base + ss]            = __float2half(v0);
                C[base + 4096 + ss]     = __float2half(v1);
                C[base + ss + 8]        = __float2half(v2);
                C[base + 4096 + ss + 8] = __float2half(v3);
            }
        }
    }
}

// ---------------------------------------------------------------------------
// Output GEMM: out[M,512] = oh @ WoT^T + bo (float out)
// ---------------------------------------------------------------------------
__global__ __launch_bounds__(256, 2)
void out_gemm(const __half* __restrict__ Oh, const __half* __restrict__ Wto,
              const float* __restrict__ bias, float* __restrict__ C)
{
    extern __shared__ __align__(16) __half smem[];
    __half* As = smem;
    __half* Bs = smem + 3 * 128 * 64;

    const __half* Ab = Oh + (size_t)blockIdx.y * 128 * 512;
    const __half* Bb = Wto + (size_t)blockIdx.x * 128 * 512;

    float acc[2][8][4];
#pragma unroll
    for (int mt = 0; mt < 2; mt++)
#pragma unroll
        for (int nt = 0; nt < 8; nt++)
#pragma unroll
            for (int f = 0; f < 4; f++) acc[mt][nt][f] = 0.f;

    gemm_mainloop(Ab, Bb, As, Bs, acc);

    const int tid = threadIdx.x;
    const int wid = tid >> 5, lid = tid & 31;
    const int wm = wid & 3, wn = wid >> 2;
    const int gid = lid >> 2, tig = lid & 3;

#pragma unroll
    for (int mt = 0; mt < 2; mt++) {
        size_t r0 = (size_t)blockIdx.y * 128 + wm * 32 + mt * 16 + gid;
#pragma unroll
        for (int nt = 0; nt < 8; nt++) {
            int col = blockIdx.x * 128 + wn * 64 + nt * 8 + tig * 2;
            float bb0 = bias[col], bb1 = bias[col + 1];
            *reinterpret_cast<float2*>(&C[r0 * 512 + col]) =
                make_float2(acc[mt][nt][0] + bb0, acc[mt][nt][1] + bb1);
            *reinterpret_cast<float2*>(&C[(r0 + 8) * 512 + col]) =
                make_float2(acc[mt][nt][2] + bb0, acc[mt][nt][3] + bb1);
        }
    }
}

// ---------------------------------------------------------------------------
// kv via tensor cores: per (bh, chunk of 256 s):
//   C[d][n] = sum_s KT[d][s] * VTe[n][s], n<64 -> kv[d][m], n=64 -> ksum[d]
// Single-buffered smem (20KB) -> whole grid resident in one wave.
// ---------------------------------------------------------------------------
__global__ __launch_bounds__(128)
void kv_mma(const __half* __restrict__ KT, const __half* __restrict__ VT,
            float* __restrict__ KVP, float* __restrict__ KSP)
{
    __shared__ __align__(16) __half kt_s[64][72];
    __shared__ __align__(16) __half vt_s[72][72];

    const int tid = threadIdx.x;
    const int w = tid >> 5, lid = tid & 31;
    const int gid = lid >> 2, tig = lid & 3;
    const int bh = blockIdx.x, chunk = blockIdx.y;
    const int s0 = chunk * 256;

    // init vt rows 64-71 (row 64 = ones for ksum, rest zero) — written once
    for (int i = tid; i < 8 * 72; i += 128) {
        int r = 64 + i / 72, c = i % 72;
        vt_s[r][c] = __float2half((r == 64) ? 1.f : 0.f);
    }

    const __half* ktb = KT + (size_t)bh * 64 * 4096 + s0;
    const __half* vtb = VT + (size_t)bh * 64 * 4096 + s0;

    const int crow = tid >> 1;
    const int cc   = (tid & 1) * 4;

#define KV_COPY(ST)                                                                       \
    do {                                                                                  \
        _Pragma("unroll")                                                                 \
        for (int i = 0; i < 4; i++) {                                                     \
            cp_async16((uint32_t)__cvta_generic_to_shared(&kt_s[crow][(cc + i) * 8]),     \
                       ktb + (size_t)crow * 4096 + (ST) * 64 + (cc + i) * 8);             \
            cp_async16((uint32_t)__cvta_generic_to_shared(&vt_s[crow][(cc + i) * 8]),     \
                       vtb + (size_t)crow * 4096 + (ST) * 64 + (cc + i) * 8);             \
        }                                                                                 \
        cp_commit();                                                                      \
    } while (0)

    float acc[9][4];
#pragma unroll
    for (int nt = 0; nt < 9; nt++)
#pragma unroll
        for (int f = 0; f < 4; f++) acc[nt][f] = 0.f;

    for (int st = 0; st < 4; st++) {
        KV_COPY(st);
        cp_wait<0>();
        __syncthreads();

        const int m0 = w * 16;
#pragma unroll
        for (int k16 = 0; k16 < 4; k16++) {
            const int k0 = k16 * 16;
            uint32_t a[4];
            a[0] = *reinterpret_cast<const uint32_t*>(&kt_s[m0 + gid    ][k0 + tig * 2]);
            a[1] = *reinterpret_cast<const uint32_t*>(&kt_s[m0 + gid + 8][k0 + tig * 2]);
            a[2] = *reinterpret_cast<const uint32_t*>(&kt_s[m0 + gid    ][k0 + 8 + tig * 2]);
            a[3] = *reinterpret_cast<const uint32_t*>(&kt_s[m0 + gid + 8][k0 + 8 + tig * 2]);
#pragma unroll
            for (int nt = 0; nt < 9; nt++) {
                uint32_t b0 = *reinterpret_cast<const uint32_t*>(&vt_s[nt * 8 + gid][k0 + tig * 2]);
                uint32_t b1 = *reinterpret_cast<const uint32_t*>(&vt_s[nt * 8 + gid][k0 + 8 + tig * 2]);
                mma_h(acc[nt], a, b0, b1);
            }
        }
        __syncthreads();   // reads done before next stage overwrites
    }
#undef KV_COPY

    float* kvp = KVP + ((size_t)chunk * 64 + bh) * 4096;
    const int d0 = w * 16 + gid;
#pragma unroll
    for (int nt = 0; nt < 8; nt++) {
        int m = nt * 8 + tig * 2;
        *reinterpret_cast<float2*>(&kvp[d0 * 64 + m])       = make_float2(acc[nt][0], acc[nt][1]);
        *reinterpret_cast<float2*>(&kvp[(d0 + 8) * 64 + m]) = make_float2(acc[nt][2], acc[nt][3]);
    }
    if (tig == 0) {
        float* ksp = KSP + ((size_t)chunk * 64 + bh) * 64;
        ksp[d0]     = acc[8][0];
        ksp[d0 + 8] = acc[8][2];
    }
}

// ---------------------------------------------------------------------------
// Reduce kv partials -> half table
// ---------------------------------------------------------------------------
__global__ __launch_bounds__(256)
void kv_reduce(const float* __restrict__ KVP, const float* __restrict__ KSP,
               __half* __restrict__ KVH)
{
    const int bh = blockIdx.x, tid = threadIdx.x;
    __half* dst = KVH + (size_t)bh * 4160;
    for (int i = tid; i < 4096; i += 256) {
        float s = 0.f;
#pragma unroll
        for (int c = 0; c < NCHUNK; c++)
            s += KVP[((size_t)c * 64 + bh) * 4096 + i];
        int d = i >> 6, m = i & 63;
        dst[m * 64 + d] = __float2half(s);
    }
    if (tid < 64) {
        float s = 0.f;
#pragma unroll
        for (int c = 0; c < NCHUNK; c++)
            s += KSP[((size_t)c * 64 + bh) * 64 + tid];
        dst[4096 + tid] = __float2half(s);
    }
}

// ---------------------------------------------------------------------------
// Attention via mma: 256 tokens per CTA (2 q-tiles reuse the kv table).
// ---------------------------------------------------------------------------
__global__ __launch_bounds__(256)
void attn_mma(const __half* __restrict__ Q, const __half* __restrict__ KVH,
              __half* __restrict__ O)
{
    __shared__ __align__(16) __half kv_t[72][72];
    __shared__ __align__(16) __half q_s [128][72];

    const int tid = threadIdx.x;
    const int w   = tid >> 5;
    const int lid = tid & 31;
    const int gid = lid >> 2;
    const int tig = lid & 3;
    const int bh = blockIdx.x;
    const int b = bh >> 3, h = bh & 7;

    const uint4* kvg = reinterpret_cast<const uint4*>(KVH + (size_t)bh * 4160);
    for (int i = tid; i < 520; i += 256) {
        int m = i >> 3, dc = i & 7;
        *reinterpret_cast<uint4*>(&kv_t[m][dc * 8]) = kvg[i];
    }
    for (int i = tid; i < 7 * 72; i += 256)
        kv_t[65 + i / 72][i % 72] = __float2half(0.f);

    const int m0 = w * 16;

#pragma unroll 1
    for (int t = 0; t < 2; t++) {
        const int s0 = blockIdx.y * 256 + t * 128;

        if (t > 0) __syncthreads();   // previous tile's q_s reads done
        const __half2* Q2 = reinterpret_cast<const __half2*>(
            Q + ((size_t)(b * SEQ + s0)) * EMB + h * HDIM);
        for (int i = tid; i < 128 * 32; i += 256) {
            int r = i >> 5, d2 = i & 31;
            *reinterpret_cast<__half2*>(&q_s[r][d2 * 2]) = Q2[(size_t)r * 256 + d2];
        }
        __syncthreads();

        float acc[9][4];
#pragma unroll
        for (int nt = 0; nt < 9; nt++)
#pragma unroll
            for (int f = 0; f < 4; f++) acc[nt][f] = 0.f;

#pragma unroll
        for (int k16 = 0; k16 < 4; k16++) {
            const int k0 = k16 * 16;
            uint32_t a[4];
            a[0] = *reinterpret_cast<const uint32_t*>(&q_s[m0 + gid    ][k0 + tig * 2]);
            a[1] = *reinterpret_cast<const uint32_t*>(&q_s[m0 + gid + 8][k0 + tig * 2]);
            a[2] = *reinterpret_cast<const uint32_t*>(&q_s[m0 + gid    ][k0 + 8 + tig * 2]);
            a[3] = *reinterpret_cast<const uint32_t*>(&q_s[m0 + gid + 8][k0 + 8 + tig * 2]);
#pragma unroll
            for (int nt = 0; nt < 9; nt++) {
                uint32_t b0 = *reinterpret_cast<const uint32_t*>(&kv_t[nt * 8 + gid][k0 + tig * 2]);
                uint32_t b1 = *reinterpret_cast<const uint32_t*>(&kv_t[nt * 8 + gid][k0 + 8 + tig * 2]);
                mma_h(acc[nt], a, b0, b1);
            }
        }

        float den0 = __shfl_sync(0xffffffffu, acc[8][0], lid & ~3);
        float den1 = __shfl_sync(0xffffffffu, acc[8][2], lid & ~3);
        float z0 = 1.f / (den0 + 1e-6f);
        float z1 = 1.f / (den1 + 1e-6f);

        size_t row0 = (size_t)(b * SEQ + s0 + m0 + gid);
#pragma unroll
        for (int nt = 0; nt < 8; nt++) {
            int col = h * HDIM + nt * 8 + tig * 2;
            *reinterpret_cast<__half2*>(&O[row0 * EMB + col]) =
                __floats2half2_rn(acc[nt][0] * z0, acc[nt][1] * z0);
            *reinterpret_cast<__half2*>(&O[(row0 + 8) * EMB + col]) =
                __floats2half2_rn(acc[nt][2] * z1, acc[nt][3] * z1);
        }
    }
}

// ---------------------------------------------------------------------------
extern "C" void kernel_launch(void* const* d_in, const int* in_sizes, int n_in,
                              void* d_out, int out_size)
{
    const float* x  = (const float*)d_in[0];
    const float* Wq = (const float*)d_in[1];
    const float* bq = (const float*)d_in[2];
    const float* Wk = (const float*)d_in[3];
    const float* bk = (const float*)d_in[4];
    const float* Wv = (const float*)d_in[5];
    const float* bv = (const float*)d_in[6];
    const float* Wo = (const float*)d_in[7];
    const float* bo = (const float*)d_in[8];
    float* out = (float*)d_out;

    __half *xh, *qh, *kt, *vt, *oh, *wth, *kvh;
    float *kvp, *ksp;
    cudaGetSymbolAddress((void**)&xh,  g_xh);
    cudaGetSymbolAddress((void**)&qh,  g_qh);
    cudaGetSymbolAddress((void**)&kt,  g_kt);
    cudaGetSymbolAddress((void**)&vt,  g_vt);
    cudaGetSymbolAddress((void**)&oh,  g_oh);
    cudaGetSymbolAddress((void**)&wth, g_wth);
    cudaGetSymbolAddress((void**)&kvh, g_kvh);
    cudaGetSymbolAddress((void**)&kvp, g_kvp);
    cudaGetSymbolAddress((void**)&ksp, g_ksp);

    cudaFuncSetAttribute(qkv_gemm, cudaFuncAttributeMaxDynamicSharedMemorySize, GEMM_SMEM_BYTES);
    cudaFuncSetAttribute(out_gemm, cudaFuncAttributeMaxDynamicSharedMemorySize, GEMM_SMEM_BYTES);

    int n4 = BS_ROWS * EMB / 4;
    f2h_kernel<<<n4 / 256, 256>>>(x, xh, n4);
    t512h4<<<dim3(16, 16, 4), 256>>>(Wq, Wk, Wv, Wo, wth);

    qkv_gemm<<<dim3(4, 256, 3), 256, GEMM_SMEM_BYTES>>>(xh, wth, bq, bk, bv, qh, kt, vt);

    kv_mma<<<dim3(64, NCHUNK), 128>>>(kt, vt, kvp, ksp);
    kv_reduce<<<64, 256>>>(kvp, ksp, kvh);
    attn_mma<<<dim3(64, 16), 256>>>(qh, kvh, oh);

    out_gemm<<<dim3(4, 256), 256, GEMM_SMEM_BYTES>>>(oh, wth + 3 * EMB * EMB, bo, out);
}